// round 5
// baseline (speedup 1.0000x reference)
#include <cuda_runtime.h>
#include <cuda_bf16.h>

// Problem constants
#define B_ 4
#define S_ 2048
#define D_ 1024
#define H_ 16
#define DH_ 64
#define N3D 3072           // 3*D
#define M_ (B_ * S_)       // 8192 rows

// Scratch (device globals: allocation-free rule)
__device__ float g_q[B_ * H_ * S_ * DH_];   // [bh][s][dh], 32MB
__device__ float g_k[B_ * H_ * S_ * DH_];
__device__ float g_v[B_ * H_ * S_ * DH_];
__device__ float g_ctx[M_ * D_];            // [b*S+s][d], 32MB

// ---------------------------------------------------------------------------
// Kernel 1: QKV projection. C[8192,3072] = X[8192,1024] @ W[1024,3072] + b,
// epilogue scatters into head-major q/k/v layouts.
// 128x128 tile, BK=16, 256 threads, 8x8 per thread.
// ---------------------------------------------------------------------------
__global__ __launch_bounds__(256) void qkv_gemm_kernel(
    const float* __restrict__ X, const float* __restrict__ W,
    const float* __restrict__ Bias) {
  __shared__ float As[16][132];   // A stored transposed [k][m], padded
  __shared__ float Bs[16][128];   // [k][n]

  const int bn0 = blockIdx.x * 128;   // col into 3072
  const int bm0 = blockIdx.y * 128;   // row into 8192
  const int tid = threadIdx.x;

  const int rowBase = (tid >> 4) * 8;     // 0..120
  const int colBase = (tid & 15) * 8;     // 0..120

  const int arow = tid >> 2;              // 0..63
  const int acol = (tid & 3) * 4;         // 0,4,8,12
  const int brow = tid >> 5;              // 0..7
  const int bcol = (tid & 31) * 4;        // 0..124

  float c[8][8];
#pragma unroll
  for (int i = 0; i < 8; ++i)
#pragma unroll
    for (int j = 0; j < 8; ++j) c[i][j] = 0.f;

  for (int k0 = 0; k0 < D_; k0 += 16) {
    float4 a0 = *(const float4*)&X[(bm0 + arow) * D_ + k0 + acol];
    float4 a1 = *(const float4*)&X[(bm0 + arow + 64) * D_ + k0 + acol];
    float4 b0 = *(const float4*)&W[(k0 + brow) * N3D + bn0 + bcol];
    float4 b1 = *(const float4*)&W[(k0 + brow + 8) * N3D + bn0 + bcol];
    __syncthreads();
    As[acol + 0][arow] = a0.x; As[acol + 1][arow] = a0.y;
    As[acol + 2][arow] = a0.z; As[acol + 3][arow] = a0.w;
    As[acol + 0][arow + 64] = a1.x; As[acol + 1][arow + 64] = a1.y;
    As[acol + 2][arow + 64] = a1.z; As[acol + 3][arow + 64] = a1.w;
    *(float4*)&Bs[brow][bcol] = b0;
    *(float4*)&Bs[brow + 8][bcol] = b1;
    __syncthreads();
#pragma unroll
    for (int kk = 0; kk < 16; ++kk) {
      float4 aA = *(const float4*)&As[kk][rowBase];
      float4 aB = *(const float4*)&As[kk][rowBase + 4];
      float4 bA = *(const float4*)&Bs[kk][colBase];
      float4 bB = *(const float4*)&Bs[kk][colBase + 4];
      float a[8] = {aA.x, aA.y, aA.z, aA.w, aB.x, aB.y, aB.z, aB.w};
      float b[8] = {bA.x, bA.y, bA.z, bA.w, bB.x, bB.y, bB.z, bB.w};
#pragma unroll
      for (int i = 0; i < 8; ++i)
#pragma unroll
        for (int j = 0; j < 8; ++j) c[i][j] += a[i] * b[j];
    }
  }

  // epilogue: + bias, scatter to head-major q/k/v
  float4 bias0 = *(const float4*)&Bias[bn0 + colBase];
  float4 bias1 = *(const float4*)&Bias[bn0 + colBase + 4];
  float bb0[4] = {bias0.x, bias0.y, bias0.z, bias0.w};
  float bb1[4] = {bias1.x, bias1.y, bias1.z, bias1.w};

#pragma unroll
  for (int jg = 0; jg < 2; ++jg) {
    int cidx = bn0 + colBase + jg * 4;
    int which = cidx >> 10;       // 0=q,1=k,2=v
    int dd = cidx & 1023;
    int h = dd >> 6;
    int dh = dd & 63;
    float* dst = (which == 0) ? g_q : (which == 1) ? g_k : g_v;
    float* biasj = jg ? bb1 : bb0;
#pragma unroll
    for (int i = 0; i < 8; ++i) {
      int m = bm0 + rowBase + i;
      int bb = m >> 11;           // /2048
      int s = m & 2047;
      float4 v;
      v.x = c[i][jg * 4 + 0] + biasj[0];
      v.y = c[i][jg * 4 + 1] + biasj[1];
      v.z = c[i][jg * 4 + 2] + biasj[2];
      v.w = c[i][jg * 4 + 3] + biasj[3];
      *(float4*)&dst[(((bb << 4) + h) * S_ + s) * DH_ + dh] = v;
    }
  }
}

// ---------------------------------------------------------------------------
// Kernel 2: fused attention (flash-style), fp32, online softmax.
// Grid: (S/64, B*H). Block 256. 64 q-rows x 64 k-cols per tile, DH=64.
// Thread (ty,tx): ty=tid/16 owns q-rows 4ty..4ty+3.
//   score phase: cols {tx, tx+16, tx+32, tx+48} (consecutive-row K reads)
//   PV/output phase: d-cols 4tx..4tx+3
// ---------------------------------------------------------------------------
#define SKV 68   // padded smem row stride (floats)
#define ATTN_SMEM (4 * 64 * SKV * 4)

__global__ __launch_bounds__(256, 2) void attn_kernel(const int* __restrict__ mask) {
  extern __shared__ float sm[];
  float* Qs = sm;                 // 64 x SKV
  float* Ks = sm + 64 * SKV;
  float* Vs = sm + 2 * 64 * SKV;
  float* Ps = sm + 3 * 64 * SKV;

  const int qb = blockIdx.x;
  const int bh = blockIdx.y;
  const int b = bh >> 4;
  const int h = bh & 15;
  const int qm0 = qb * 64;

  const float* Qg = g_q + bh * (S_ * DH_) + qm0 * DH_;
  const float* Kg = g_k + bh * (S_ * DH_);
  const float* Vg = g_v + bh * (S_ * DH_);
  const int* Mg = mask + b * (S_ * S_) + qm0 * S_;

  const int tid = threadIdx.x;
  const int ty = tid >> 4;
  const int tx = tid & 15;
  const int r0 = ty * 4;
  const int cPV = tx * 4;

  // load Q tile (64x64) into padded smem
#pragma unroll
  for (int i = 0; i < 4; ++i) {
    int idx4 = tid + 256 * i;
    int row = idx4 >> 4;
    int col = (idx4 & 15) * 4;
    *(float4*)&Qs[row * SKV + col] = *(const float4*)&Qg[row * 64 + col];
  }

  float O[4][4];
  float mi[4], li[4];
#pragma unroll
  for (int i = 0; i < 4; ++i) {
    mi[i] = -1e30f;
    li[i] = 0.f;
#pragma unroll
    for (int j = 0; j < 4; ++j) O[i][j] = 0.f;
  }

  for (int kn0 = 0; kn0 < S_; kn0 += 64) {
    // load K,V tiles
#pragma unroll
    for (int i = 0; i < 4; ++i) {
      int idx4 = tid + 256 * i;
      int row = idx4 >> 4;
      int col = (idx4 & 15) * 4;
      *(float4*)&Ks[row * SKV + col] =
          *(const float4*)&Kg[(kn0 + row) * 64 + col];
      *(float4*)&Vs[row * SKV + col] =
          *(const float4*)&Vg[(kn0 + row) * 64 + col];
    }
    __syncthreads();

    // scores: s[i][j] = Q[r0+i] . K[tx+16j]
    float s[4][4];
#pragma unroll
    for (int i = 0; i < 4; ++i)
#pragma unroll
      for (int j = 0; j < 4; ++j) s[i][j] = 0.f;

#pragma unroll
    for (int k = 0; k < 64; k += 4) {
      float4 qv[4], kv[4];
#pragma unroll
      for (int i = 0; i < 4; ++i)
        qv[i] = *(const float4*)&Qs[(r0 + i) * SKV + k];
#pragma unroll
      for (int j = 0; j < 4; ++j)
        kv[j] = *(const float4*)&Ks[(tx + 16 * j) * SKV + k];
#pragma unroll
      for (int i = 0; i < 4; ++i)
#pragma unroll
        for (int j = 0; j < 4; ++j)
          s[i][j] += qv[i].x * kv[j].x + qv[i].y * kv[j].y +
                     qv[i].z * kv[j].z + qv[i].w * kv[j].w;
    }

    // mask + scale + online softmax, stage P into smem
#pragma unroll
    for (int i = 0; i < 4; ++i) {
      int row = r0 + i;
      const int* mrow = Mg + row * S_ + kn0;
      float sv[4];
#pragma unroll
      for (int j = 0; j < 4; ++j) {
        int mv = mrow[tx + 16 * j];
        sv[j] = mv ? s[i][j] * 0.125f : -1000.0f;
      }
      float rmax = fmaxf(fmaxf(sv[0], sv[1]), fmaxf(sv[2], sv[3]));
#pragma unroll
      for (int o = 8; o > 0; o >>= 1)
        rmax = fmaxf(rmax, __shfl_xor_sync(0xffffffffu, rmax, o));
      float mnew = fmaxf(mi[i], rmax);
      float corr = __expf(mi[i] - mnew);
      mi[i] = mnew;
      float rsum = 0.f;
#pragma unroll
      for (int j = 0; j < 4; ++j) {
        float p = __expf(sv[j] - mnew);
        rsum += p;
        Ps[row * SKV + tx + 16 * j] = p;
      }
#pragma unroll
      for (int o = 8; o > 0; o >>= 1)
        rsum += __shfl_xor_sync(0xffffffffu, rsum, o);
      li[i] = li[i] * corr + rsum;
      O[i][0] *= corr; O[i][1] *= corr; O[i][2] *= corr; O[i][3] *= corr;
    }
    __syncthreads();

    // PV: O[i][dc] += sum_n P[r0+i][n] * V[n][cPV+dc]
#pragma unroll
    for (int n = 0; n < 64; n += 4) {
      float4 pr[4], vr[4];
#pragma unroll
      for (int i = 0; i < 4; ++i)
        pr[i] = *(const float4*)&Ps[(r0 + i) * SKV + n];
#pragma unroll
      for (int j = 0; j < 4; ++j)
        vr[j] = *(const float4*)&Vs[(n + j) * SKV + cPV];
#pragma unroll
      for (int i = 0; i < 4; ++i) {
        O[i][0] += pr[i].x * vr[0].x + pr[i].y * vr[1].x +
                   pr[i].z * vr[2].x + pr[i].w * vr[3].x;
        O[i][1] += pr[i].x * vr[0].y + pr[i].y * vr[1].y +
                   pr[i].z * vr[2].y + pr[i].w * vr[3].y;
        O[i][2] += pr[i].x * vr[0].z + pr[i].y * vr[1].z +
                   pr[i].z * vr[2].z + pr[i].w * vr[3].z;
        O[i][3] += pr[i].x * vr[0].w + pr[i].y * vr[1].w +
                   pr[i].z * vr[2].w + pr[i].w * vr[3].w;
      }
    }
    __syncthreads();
  }

  // normalize + write ctx in [B,S,D] layout
#pragma unroll
  for (int i = 0; i < 4; ++i) {
    float inv = 1.0f / li[i];
    int q = qm0 + r0 + i;
    float4 v = make_float4(O[i][0] * inv, O[i][1] * inv,
                           O[i][2] * inv, O[i][3] * inv);
    *(float4*)&g_ctx[(b * S_ + q) * D_ + h * 64 + cPV] = v;
  }
}

// ---------------------------------------------------------------------------
// Kernel 3: output projection. out[8192,1024] = ctx @ Wout + b_out
// ---------------------------------------------------------------------------
__global__ __launch_bounds__(256) void out_gemm_kernel(
    const float* __restrict__ Wout, const float* __restrict__ Bias,
    float* __restrict__ out) {
  __shared__ float As[16][132];
  __shared__ float Bs[16][128];

  const int bn0 = blockIdx.x * 128;   // col into 1024
  const int bm0 = blockIdx.y * 128;   // row into 8192
  const int tid = threadIdx.x;

  const int rowBase = (tid >> 4) * 8;
  const int colBase = (tid & 15) * 8;
  const int arow = tid >> 2;
  const int acol = (tid & 3) * 4;
  const int brow = tid >> 5;
  const int bcol = (tid & 31) * 4;

  float c[8][8];
#pragma unroll
  for (int i = 0; i < 8; ++i)
#pragma unroll
    for (int j = 0; j < 8; ++j) c[i][j] = 0.f;

  for (int k0 = 0; k0 < D_; k0 += 16) {
    float4 a0 = *(const float4*)&g_ctx[(bm0 + arow) * D_ + k0 + acol];
    float4 a1 = *(const float4*)&g_ctx[(bm0 + arow + 64) * D_ + k0 + acol];
    float4 b0 = *(const float4*)&Wout[(k0 + brow) * D_ + bn0 + bcol];
    float4 b1 = *(const float4*)&Wout[(k0 + brow + 8) * D_ + bn0 + bcol];
    __syncthreads();
    As[acol + 0][arow] = a0.x; As[acol + 1][arow] = a0.y;
    As[acol + 2][arow] = a0.z; As[acol + 3][arow] = a0.w;
    As[acol + 0][arow + 64] = a1.x; As[acol + 1][arow + 64] = a1.y;
    As[acol + 2][arow + 64] = a1.z; As[acol + 3][arow + 64] = a1.w;
    *(float4*)&Bs[brow][bcol] = b0;
    *(float4*)&Bs[brow + 8][bcol] = b1;
    __syncthreads();
#pragma unroll
    for (int kk = 0; kk < 16; ++kk) {
      float4 aA = *(const float4*)&As[kk][rowBase];
      float4 aB = *(const float4*)&As[kk][rowBase + 4];
      float4 bA = *(const float4*)&Bs[kk][colBase];
      float4 bB = *(const float4*)&Bs[kk][colBase + 4];
      float a[8] = {aA.x, aA.y, aA.z, aA.w, aB.x, aB.y, aB.z, aB.w};
      float b[8] = {bA.x, bA.y, bA.z, bA.w, bB.x, bB.y, bB.z, bB.w};
#pragma unroll
      for (int i = 0; i < 8; ++i)
#pragma unroll
        for (int j = 0; j < 8; ++j) c[i][j] += a[i] * b[j];
    }
  }

  float4 bias0 = *(const float4*)&Bias[bn0 + colBase];
  float4 bias1 = *(const float4*)&Bias[bn0 + colBase + 4];
#pragma unroll
  for (int i = 0; i < 8; ++i) {
    int m = bm0 + rowBase + i;
    float4 v0 = make_float4(c[i][0] + bias0.x, c[i][1] + bias0.y,
                            c[i][2] + bias0.z, c[i][3] + bias0.w);
    float4 v1 = make_float4(c[i][4] + bias1.x, c[i][5] + bias1.y,
                            c[i][6] + bias1.z, c[i][7] + bias1.w);
    *(float4*)&out[m * D_ + bn0 + colBase] = v0;
    *(float4*)&out[m * D_ + bn0 + colBase + 4] = v1;
  }
}

// ---------------------------------------------------------------------------
extern "C" void kernel_launch(void* const* d_in, const int* in_sizes, int n_in,
                              void* d_out, int out_size) {
  const float* x     = (const float*)d_in[0];
  const int*   mask  = (const int*)d_in[1];
  const float* w_qkv = (const float*)d_in[2];
  const float* b_qkv = (const float*)d_in[3];
  const float* w_out = (const float*)d_in[4];
  const float* b_out = (const float*)d_in[5];
  float* out = (float*)d_out;

  // Allow 69.6KB dynamic smem for the attention kernel (idempotent; also set
  // during the pre-capture correctness call).
  cudaFuncSetAttribute(attn_kernel,
                       cudaFuncAttributeMaxDynamicSharedMemorySize, ATTN_SMEM);

  qkv_gemm_kernel<<<dim3(N3D / 128, M_ / 128), 256>>>(x, w_qkv, b_qkv);
  attn_kernel<<<dim3(S_ / 64, B_ * H_), 256, ATTN_SMEM>>>(mask);
  out_gemm_kernel<<<dim3(D_ / 128, M_ / 128), 256>>>(w_out, b_out, out);
}

// round 6
// speedup vs baseline: 1.0009x; 1.0009x over previous
#include <cuda_runtime.h>
#include <cuda_bf16.h>

// Problem constants
#define B_ 4
#define S_ 2048
#define D_ 1024
#define H_ 16
#define DH_ 64
#define N3D 3072           // 3*D
#define M_ (B_ * S_)       // 8192 rows

// Scratch (device globals: allocation-free rule)
__device__ float g_q[B_ * H_ * S_ * DH_];   // [bh][s][dh], 32MB
__device__ float g_k[B_ * H_ * S_ * DH_];
__device__ float g_v[B_ * H_ * S_ * DH_];
__device__ float g_ctx[M_ * D_];            // [b*S+s][d], 32MB

// ---------------------------------------------------------------------------
// Kernel 1: QKV projection. C[8192,3072] = X[8192,1024] @ W[1024,3072] + b,
// epilogue scatters into head-major q/k/v layouts.
// 128x128 tile, BK=16, 256 threads, 8x8 per thread.
// ---------------------------------------------------------------------------
__global__ __launch_bounds__(256) void qkv_gemm_kernel(
    const float* __restrict__ X, const float* __restrict__ W,
    const float* __restrict__ Bias) {
  __shared__ float As[16][132];   // A stored transposed [k][m], padded
  __shared__ float Bs[16][128];   // [k][n]

  const int bn0 = blockIdx.x * 128;   // col into 3072
  const int bm0 = blockIdx.y * 128;   // row into 8192
  const int tid = threadIdx.x;

  const int rowBase = (tid >> 4) * 8;     // 0..120
  const int colBase = (tid & 15) * 8;     // 0..120

  const int arow = tid >> 2;              // 0..63
  const int acol = (tid & 3) * 4;         // 0,4,8,12
  const int brow = tid >> 5;              // 0..7
  const int bcol = (tid & 31) * 4;        // 0..124

  float c[8][8];
#pragma unroll
  for (int i = 0; i < 8; ++i)
#pragma unroll
    for (int j = 0; j < 8; ++j) c[i][j] = 0.f;

  for (int k0 = 0; k0 < D_; k0 += 16) {
    float4 a0 = *(const float4*)&X[(bm0 + arow) * D_ + k0 + acol];
    float4 a1 = *(const float4*)&X[(bm0 + arow + 64) * D_ + k0 + acol];
    float4 b0 = *(const float4*)&W[(k0 + brow) * N3D + bn0 + bcol];
    float4 b1 = *(const float4*)&W[(k0 + brow + 8) * N3D + bn0 + bcol];
    __syncthreads();
    As[acol + 0][arow] = a0.x; As[acol + 1][arow] = a0.y;
    As[acol + 2][arow] = a0.z; As[acol + 3][arow] = a0.w;
    As[acol + 0][arow + 64] = a1.x; As[acol + 1][arow + 64] = a1.y;
    As[acol + 2][arow + 64] = a1.z; As[acol + 3][arow + 64] = a1.w;
    *(float4*)&Bs[brow][bcol] = b0;
    *(float4*)&Bs[brow + 8][bcol] = b1;
    __syncthreads();
#pragma unroll
    for (int kk = 0; kk < 16; ++kk) {
      float4 aA = *(const float4*)&As[kk][rowBase];
      float4 aB = *(const float4*)&As[kk][rowBase + 4];
      float4 bA = *(const float4*)&Bs[kk][colBase];
      float4 bB = *(const float4*)&Bs[kk][colBase + 4];
      float a[8] = {aA.x, aA.y, aA.z, aA.w, aB.x, aB.y, aB.z, aB.w};
      float b[8] = {bA.x, bA.y, bA.z, bA.w, bB.x, bB.y, bB.z, bB.w};
#pragma unroll
      for (int i = 0; i < 8; ++i)
#pragma unroll
        for (int j = 0; j < 8; ++j) c[i][j] += a[i] * b[j];
    }
  }

  // epilogue: + bias, scatter to head-major q/k/v
  float4 bias0 = *(const float4*)&Bias[bn0 + colBase];
  float4 bias1 = *(const float4*)&Bias[bn0 + colBase + 4];
  float bb0[4] = {bias0.x, bias0.y, bias0.z, bias0.w};
  float bb1[4] = {bias1.x, bias1.y, bias1.z, bias1.w};

#pragma unroll
  for (int jg = 0; jg < 2; ++jg) {
    int cidx = bn0 + colBase + jg * 4;
    int which = cidx >> 10;       // 0=q,1=k,2=v
    int dd = cidx & 1023;
    int h = dd >> 6;
    int dh = dd & 63;
    float* dst = (which == 0) ? g_q : (which == 1) ? g_k : g_v;
    float* biasj = jg ? bb1 : bb0;
#pragma unroll
    for (int i = 0; i < 8; ++i) {
      int m = bm0 + rowBase + i;
      int bb = m >> 11;           // /2048
      int s = m & 2047;
      float4 v;
      v.x = c[i][jg * 4 + 0] + biasj[0];
      v.y = c[i][jg * 4 + 1] + biasj[1];
      v.z = c[i][jg * 4 + 2] + biasj[2];
      v.w = c[i][jg * 4 + 3] + biasj[3];
      *(float4*)&dst[(((bb << 4) + h) * S_ + s) * DH_ + dh] = v;
    }
  }
}

// ---------------------------------------------------------------------------
// Kernel 2: fused attention (flash-style), fp32, online softmax.
// Grid: (S/64, B*H). Block 256. 64 q-rows x 64 k-cols per tile, DH=64.
// Thread (ty,tx): ty=tid/16 owns q-rows 4ty..4ty+3.
//   score phase: cols {tx, tx+16, tx+32, tx+48} (consecutive-row K reads)
//   PV/output phase: d-cols 4tx..4tx+3
// ---------------------------------------------------------------------------
#define SKV 68   // padded smem row stride (floats)
#define ATTN_SMEM (4 * 64 * SKV * 4)

__global__ __launch_bounds__(256, 2) void attn_kernel(const int* __restrict__ mask) {
  extern __shared__ float sm[];
  float* Qs = sm;                 // 64 x SKV
  float* Ks = sm + 64 * SKV;
  float* Vs = sm + 2 * 64 * SKV;
  float* Ps = sm + 3 * 64 * SKV;

  const int qb = blockIdx.x;
  const int bh = blockIdx.y;
  const int b = bh >> 4;
  const int h = bh & 15;
  const int qm0 = qb * 64;

  const float* Qg = g_q + bh * (S_ * DH_) + qm0 * DH_;
  const float* Kg = g_k + bh * (S_ * DH_);
  const float* Vg = g_v + bh * (S_ * DH_);
  const int* Mg = mask + b * (S_ * S_) + qm0 * S_;

  const int tid = threadIdx.x;
  const int ty = tid >> 4;
  const int tx = tid & 15;
  const int r0 = ty * 4;
  const int cPV = tx * 4;

  // load Q tile (64x64) into padded smem
#pragma unroll
  for (int i = 0; i < 4; ++i) {
    int idx4 = tid + 256 * i;
    int row = idx4 >> 4;
    int col = (idx4 & 15) * 4;
    *(float4*)&Qs[row * SKV + col] = *(const float4*)&Qg[row * 64 + col];
  }

  float O[4][4];
  float mi[4], li[4];
#pragma unroll
  for (int i = 0; i < 4; ++i) {
    mi[i] = -1e30f;
    li[i] = 0.f;
#pragma unroll
    for (int j = 0; j < 4; ++j) O[i][j] = 0.f;
  }

  for (int kn0 = 0; kn0 < S_; kn0 += 64) {
    // load K,V tiles
#pragma unroll
    for (int i = 0; i < 4; ++i) {
      int idx4 = tid + 256 * i;
      int row = idx4 >> 4;
      int col = (idx4 & 15) * 4;
      *(float4*)&Ks[row * SKV + col] =
          *(const float4*)&Kg[(kn0 + row) * 64 + col];
      *(float4*)&Vs[row * SKV + col] =
          *(const float4*)&Vg[(kn0 + row) * 64 + col];
    }
    __syncthreads();

    // scores: s[i][j] = Q[r0+i] . K[tx+16j]
    float s[4][4];
#pragma unroll
    for (int i = 0; i < 4; ++i)
#pragma unroll
      for (int j = 0; j < 4; ++j) s[i][j] = 0.f;

#pragma unroll
    for (int k = 0; k < 64; k += 4) {
      float4 qv[4], kv[4];
#pragma unroll
      for (int i = 0; i < 4; ++i)
        qv[i] = *(const float4*)&Qs[(r0 + i) * SKV + k];
#pragma unroll
      for (int j = 0; j < 4; ++j)
        kv[j] = *(const float4*)&Ks[(tx + 16 * j) * SKV + k];
#pragma unroll
      for (int i = 0; i < 4; ++i)
#pragma unroll
        for (int j = 0; j < 4; ++j)
          s[i][j] += qv[i].x * kv[j].x + qv[i].y * kv[j].y +
                     qv[i].z * kv[j].z + qv[i].w * kv[j].w;
    }

    // mask + scale + online softmax, stage P into smem
#pragma unroll
    for (int i = 0; i < 4; ++i) {
      int row = r0 + i;
      const int* mrow = Mg + row * S_ + kn0;
      float sv[4];
#pragma unroll
      for (int j = 0; j < 4; ++j) {
        int mv = mrow[tx + 16 * j];
        sv[j] = mv ? s[i][j] * 0.125f : -1000.0f;
      }
      float rmax = fmaxf(fmaxf(sv[0], sv[1]), fmaxf(sv[2], sv[3]));
#pragma unroll
      for (int o = 8; o > 0; o >>= 1)
        rmax = fmaxf(rmax, __shfl_xor_sync(0xffffffffu, rmax, o));
      float mnew = fmaxf(mi[i], rmax);
      float corr = __expf(mi[i] - mnew);
      mi[i] = mnew;
      float rsum = 0.f;
#pragma unroll
      for (int j = 0; j < 4; ++j) {
        float p = __expf(sv[j] - mnew);
        rsum += p;
        Ps[row * SKV + tx + 16 * j] = p;
      }
#pragma unroll
      for (int o = 8; o > 0; o >>= 1)
        rsum += __shfl_xor_sync(0xffffffffu, rsum, o);
      li[i] = li[i] * corr + rsum;
      O[i][0] *= corr; O[i][1] *= corr; O[i][2] *= corr; O[i][3] *= corr;
    }
    __syncthreads();

    // PV: O[i][dc] += sum_n P[r0+i][n] * V[n][cPV+dc]
#pragma unroll
    for (int n = 0; n < 64; n += 4) {
      float4 pr[4], vr[4];
#pragma unroll
      for (int i = 0; i < 4; ++i)
        pr[i] = *(const float4*)&Ps[(r0 + i) * SKV + n];
#pragma unroll
      for (int j = 0; j < 4; ++j)
        vr[j] = *(const float4*)&Vs[(n + j) * SKV + cPV];
#pragma unroll
      for (int i = 0; i < 4; ++i) {
        O[i][0] += pr[i].x * vr[0].x + pr[i].y * vr[1].x +
                   pr[i].z * vr[2].x + pr[i].w * vr[3].x;
        O[i][1] += pr[i].x * vr[0].y + pr[i].y * vr[1].y +
                   pr[i].z * vr[2].y + pr[i].w * vr[3].y;
        O[i][2] += pr[i].x * vr[0].z + pr[i].y * vr[1].z +
                   pr[i].z * vr[2].z + pr[i].w * vr[3].z;
        O[i][3] += pr[i].x * vr[0].w + pr[i].y * vr[1].w +
                   pr[i].z * vr[2].w + pr[i].w * vr[3].w;
      }
    }
    __syncthreads();
  }

  // normalize + write ctx in [B,S,D] layout
#pragma unroll
  for (int i = 0; i < 4; ++i) {
    float inv = 1.0f / li[i];
    int q = qm0 + r0 + i;
    float4 v = make_float4(O[i][0] * inv, O[i][1] * inv,
                           O[i][2] * inv, O[i][3] * inv);
    *(float4*)&g_ctx[(b * S_ + q) * D_ + h * 64 + cPV] = v;
  }
}

// ---------------------------------------------------------------------------
// Kernel 3: output projection. out[8192,1024] = ctx @ Wout + b_out
// ---------------------------------------------------------------------------
__global__ __launch_bounds__(256) void out_gemm_kernel(
    const float* __restrict__ Wout, const float* __restrict__ Bias,
    float* __restrict__ out) {
  __shared__ float As[16][132];
  __shared__ float Bs[16][128];

  const int bn0 = blockIdx.x * 128;   // col into 1024
  const int bm0 = blockIdx.y * 128;   // row into 8192
  const int tid = threadIdx.x;

  const int rowBase = (tid >> 4) * 8;
  const int colBase = (tid & 15) * 8;
  const int arow = tid >> 2;
  const int acol = (tid & 3) * 4;
  const int brow = tid >> 5;
  const int bcol = (tid & 31) * 4;

  float c[8][8];
#pragma unroll
  for (int i = 0; i < 8; ++i)
#pragma unroll
    for (int j = 0; j < 8; ++j) c[i][j] = 0.f;

  for (int k0 = 0; k0 < D_; k0 += 16) {
    float4 a0 = *(const float4*)&g_ctx[(bm0 + arow) * D_ + k0 + acol];
    float4 a1 = *(const float4*)&g_ctx[(bm0 + arow + 64) * D_ + k0 + acol];
    float4 b0 = *(const float4*)&Wout[(k0 + brow) * D_ + bn0 + bcol];
    float4 b1 = *(const float4*)&Wout[(k0 + brow + 8) * D_ + bn0 + bcol];
    __syncthreads();
    As[acol + 0][arow] = a0.x; As[acol + 1][arow] = a0.y;
    As[acol + 2][arow] = a0.z; As[acol + 3][arow] = a0.w;
    As[acol + 0][arow + 64] = a1.x; As[acol + 1][arow + 64] = a1.y;
    As[acol + 2][arow + 64] = a1.z; As[acol + 3][arow + 64] = a1.w;
    *(float4*)&Bs[brow][bcol] = b0;
    *(float4*)&Bs[brow + 8][bcol] = b1;
    __syncthreads();
#pragma unroll
    for (int kk = 0; kk < 16; ++kk) {
      float4 aA = *(const float4*)&As[kk][rowBase];
      float4 aB = *(const float4*)&As[kk][rowBase + 4];
      float4 bA = *(const float4*)&Bs[kk][colBase];
      float4 bB = *(const float4*)&Bs[kk][colBase + 4];
      float a[8] = {aA.x, aA.y, aA.z, aA.w, aB.x, aB.y, aB.z, aB.w};
      float b[8] = {bA.x, bA.y, bA.z, bA.w, bB.x, bB.y, bB.z, bB.w};
#pragma unroll
      for (int i = 0; i < 8; ++i)
#pragma unroll
        for (int j = 0; j < 8; ++j) c[i][j] += a[i] * b[j];
    }
  }

  float4 bias0 = *(const float4*)&Bias[bn0 + colBase];
  float4 bias1 = *(const float4*)&Bias[bn0 + colBase + 4];
#pragma unroll
  for (int i = 0; i < 8; ++i) {
    int m = bm0 + rowBase + i;
    float4 v0 = make_float4(c[i][0] + bias0.x, c[i][1] + bias0.y,
                            c[i][2] + bias0.z, c[i][3] + bias0.w);
    float4 v1 = make_float4(c[i][4] + bias1.x, c[i][5] + bias1.y,
                            c[i][6] + bias1.z, c[i][7] + bias1.w);
    *(float4*)&out[m * D_ + bn0 + colBase] = v0;
    *(float4*)&out[m * D_ + bn0 + colBase + 4] = v1;
  }
}

// ---------------------------------------------------------------------------
extern "C" void kernel_launch(void* const* d_in, const int* in_sizes, int n_in,
                              void* d_out, int out_size) {
  const float* x     = (const float*)d_in[0];
  const int*   mask  = (const int*)d_in[1];
  const float* w_qkv = (const float*)d_in[2];
  const float* b_qkv = (const float*)d_in[3];
  const float* w_out = (const float*)d_in[4];
  const float* b_out = (const float*)d_in[5];
  float* out = (float*)d_out;

  // Allow 69.6KB dynamic smem for the attention kernel (idempotent; also set
  // during the pre-capture correctness call).
  cudaFuncSetAttribute(attn_kernel,
                       cudaFuncAttributeMaxDynamicSharedMemorySize, ATTN_SMEM);

  qkv_gemm_kernel<<<dim3(N3D / 128, M_ / 128), 256>>>(x, w_qkv, b_qkv);
  attn_kernel<<<dim3(S_ / 64, B_ * H_), 256, ATTN_SMEM>>>(mask);
  out_gemm_kernel<<<dim3(D_ / 128, M_ / 128), 256>>>(w_out, b_out, out);
}

// round 8
// speedup vs baseline: 1.2835x; 1.2823x over previous
#include <cuda_runtime.h>
#include <cuda_bf16.h>
#include <cstdint>

// Problem constants
#define B_ 4
#define S_ 2048
#define D_ 1024
#define H_ 16
#define DH_ 64
#define N3D 3072           // 3*D
#define M_ (B_ * S_)       // 8192 rows

// ---------------------------------------------------------------------------
// Device scratch (allocation-free rule)
// ---------------------------------------------------------------------------
__device__ __align__(256) __nv_bfloat16 g_xhi[M_ * D_];
__device__ __align__(256) __nv_bfloat16 g_xlo[M_ * D_];
__device__ __align__(256) __nv_bfloat16 g_wthi[N3D * D_];   // W_qkv^T [n][k]
__device__ __align__(256) __nv_bfloat16 g_wtlo[N3D * D_];
__device__ __align__(256) __nv_bfloat16 g_wothi[D_ * D_];   // W_out^T [n][k]
__device__ __align__(256) __nv_bfloat16 g_wotlo[D_ * D_];
__device__ __align__(256) float g_q[B_ * H_ * S_ * DH_];    // fp32 head-major
__device__ __align__(256) float g_k[B_ * H_ * S_ * DH_];
__device__ __align__(256) float g_v[B_ * H_ * S_ * DH_];
__device__ __align__(256) __nv_bfloat16 g_ctxhi[M_ * D_];   // [b*S+s][d]
__device__ __align__(256) __nv_bfloat16 g_ctxlo[M_ * D_];

// ---------------------------------------------------------------------------
// PTX helpers (sm_80+ standard instructions only — no tcgen05: harness PTX
// target is plain sm_103, 'a'-suffix features are unavailable)
// ---------------------------------------------------------------------------
__device__ __forceinline__ uint32_t smem_to_u32(const void* p) {
  uint32_t a;
  asm("{ .reg .u64 t; cvta.to.shared.u64 t, %1; cvt.u32.u64 %0, t; }"
      : "=r"(a) : "l"(p));
  return a;
}

#define CP_ASYNC16(dst, src)                                              \
  asm volatile("cp.async.cg.shared.global [%0], [%1], 16;" ::"r"(dst),    \
               "l"(src) : "memory")
#define CP_COMMIT() asm volatile("cp.async.commit_group;" ::: "memory")
#define CP_WAIT1() asm volatile("cp.async.wait_group 1;" ::: "memory")
#define CP_WAIT0() asm volatile("cp.async.wait_group 0;" ::: "memory")

#define LDSM4(r, addr)                                                     \
  asm volatile(                                                            \
      "ldmatrix.sync.aligned.m8n8.x4.shared.b16 {%0,%1,%2,%3}, [%4];"      \
      : "=r"((r)[0]), "=r"((r)[1]), "=r"((r)[2]), "=r"((r)[3])             \
      : "r"(addr))

#define MMA16816(c, a, b0, b1)                                              \
  asm volatile(                                                             \
      "mma.sync.aligned.m16n8k16.row.col.f32.bf16.bf16.f32 "                \
      "{%0,%1,%2,%3}, {%4,%5,%6,%7}, {%8,%9}, {%0,%1,%2,%3};"               \
      : "+f"((c)[0]), "+f"((c)[1]), "+f"((c)[2]), "+f"((c)[3])              \
      : "r"((a)[0]), "r"((a)[1]), "r"((a)[2]), "r"((a)[3]), "r"(b0),        \
        "r"(b1))

// ---------------------------------------------------------------------------
// Converter: fp32 -> bf16 hi/lo split (element-wise, vectorized by 4)
// ---------------------------------------------------------------------------
__global__ void convert_split(const float* __restrict__ X, int n4,
                              __nv_bfloat16* __restrict__ hi,
                              __nv_bfloat16* __restrict__ lo) {
  int i = blockIdx.x * blockDim.x + threadIdx.x;
  if (i >= n4) return;
  float4 v = ((const float4*)X)[i];
  __nv_bfloat162 ha, hb, la, lb;
  ha.x = __float2bfloat16(v.x);
  ha.y = __float2bfloat16(v.y);
  hb.x = __float2bfloat16(v.z);
  hb.y = __float2bfloat16(v.w);
  la.x = __float2bfloat16(v.x - __bfloat162float(ha.x));
  la.y = __float2bfloat16(v.y - __bfloat162float(ha.y));
  lb.x = __float2bfloat16(v.z - __bfloat162float(hb.x));
  lb.y = __float2bfloat16(v.w - __bfloat162float(hb.y));
  ((__nv_bfloat162*)hi)[2 * i] = ha;
  ((__nv_bfloat162*)hi)[2 * i + 1] = hb;
  ((__nv_bfloat162*)lo)[2 * i] = la;
  ((__nv_bfloat162*)lo)[2 * i + 1] = lb;
}

// ---------------------------------------------------------------------------
// Converter: transpose W[K][N] -> WT[N][K] with bf16 hi/lo split
// ---------------------------------------------------------------------------
__global__ void transpose_convert(const float* __restrict__ W, int Kd, int Nd,
                                  __nv_bfloat16* __restrict__ WT_hi,
                                  __nv_bfloat16* __restrict__ WT_lo) {
  __shared__ float t[32][33];
  int n0 = blockIdx.x * 32, k0 = blockIdx.y * 32;
  int tx = threadIdx.x;
  for (int r = threadIdx.y; r < 32; r += 8)
    t[r][tx] = W[(size_t)(k0 + r) * Nd + n0 + tx];
  __syncthreads();
  for (int r = threadIdx.y; r < 32; r += 8) {
    float v = t[tx][r];  // = W[k0+tx][n0+r]
    __nv_bfloat16 h = __float2bfloat16(v);
    size_t o = (size_t)(n0 + r) * Kd + k0 + tx;
    WT_hi[o] = h;
    WT_lo[o] = __float2bfloat16(v - __bfloat162float(h));
  }
}

// ---------------------------------------------------------------------------
// bf16x3 GEMM via mma.sync: C[M,N] = A[M,K] @ B^T[N,K] + bias
//   A,B in K-major bf16 hi/lo. 128x128 CTA tile, BK=64, double-buffered
//   cp.async. 8 warps, 64x32 warp tiles, m16n8k16 fragments via ldmatrix.
//   Row pad: 72 bf16 (144 B) -> conflict-free ldmatrix (bank phase 4 per row).
//   mode 0: scatter into head-major g_q/g_k/g_v ; mode 1: row-major out.
// ---------------------------------------------------------------------------
#define TILE_B 18432            // 128 rows * 144 B
#define STAGE_B (4 * TILE_B)    // Ah, Al, Bh, Bl
#define GEMM_SMEM (2 * STAGE_B) // 147456 B

__device__ __forceinline__ void stage_copy(uint32_t sb,
                                           const __nv_bfloat16* gAh,
                                           const __nv_bfloat16* gAl,
                                           const __nv_bfloat16* gBh,
                                           const __nv_bfloat16* gBl,
                                           int Kdim, int kc16, int tid) {
  const __nv_bfloat16* gp[4] = {gAh, gAl, gBh, gBl};
#pragma unroll
  for (int t4 = 0; t4 < 4; ++t4) {
    uint32_t tb = sb + t4 * TILE_B;
    const char* gb = (const char*)gp[t4];
#pragma unroll
    for (int i = 0; i < 4; ++i) {
      int id = tid + 256 * i;          // 1024 chunks: 128 rows x 8 x 16B
      int row = id >> 3, c = id & 7;
      uint32_t dst = tb + row * 144 + c * 16;
      const char* src = gb + ((size_t)row * Kdim + (size_t)(kc16 + c) * 8) * 2;
      CP_ASYNC16(dst, src);
    }
  }
}

__global__ __launch_bounds__(256, 1) void mma_gemm(
    const __nv_bfloat16* __restrict__ Ah, const __nv_bfloat16* __restrict__ Al,
    const __nv_bfloat16* __restrict__ Bh, const __nv_bfloat16* __restrict__ Bl,
    const float* __restrict__ bias, int Kdim, int mode,
    float* __restrict__ outp, float* __restrict__ qp, float* __restrict__ kp,
    float* __restrict__ vp) {
  extern __shared__ __align__(1024) char smem[];
  const uint32_t sm0 = smem_to_u32(smem);
  const int tid = threadIdx.x;
  const int lane = tid & 31;
  const int wid = tid >> 5;
  const int bn0 = blockIdx.x * 128;
  const int bm0 = blockIdx.y * 128;
  const int wm = (wid >> 2) * 64;   // warp m offset in CTA tile
  const int wn = (wid & 3) * 32;    // warp n offset

  const __nv_bfloat16* gAh = Ah + (size_t)bm0 * Kdim;
  const __nv_bfloat16* gAl = Al + (size_t)bm0 * Kdim;
  const __nv_bfloat16* gBh = Bh + (size_t)bn0 * Kdim;
  const __nv_bfloat16* gBl = Bl + (size_t)bn0 * Kdim;

  float acc[4][4][4];
#pragma unroll
  for (int f = 0; f < 4; ++f)
#pragma unroll
    for (int j = 0; j < 4; ++j)
#pragma unroll
      for (int r = 0; r < 4; ++r) acc[f][j][r] = 0.f;

  const int nkt = Kdim >> 6;  // K tiles of 64
  stage_copy(sm0, gAh, gAl, gBh, gBl, Kdim, 0, tid);
  CP_COMMIT();
  stage_copy(sm0 + STAGE_B, gAh, gAl, gBh, gBl, Kdim, 8, tid);
  CP_COMMIT();

  const uint32_t lrow = lane & 15;
  const uint32_t lsel = (lane >> 4) * 16;

  for (int kt = 0; kt < nkt; ++kt) {
    if (kt == nkt - 1) CP_WAIT0(); else CP_WAIT1();
    __syncthreads();
    const uint32_t sb = sm0 + (kt & 1) * STAGE_B;
    const uint32_t aBaseH = sb + (wm + lrow) * 144 + lsel;
    const uint32_t aBaseL = aBaseH + TILE_B;
    const uint32_t bBaseH = sb + 2 * TILE_B + (wn + lrow) * 144 + lsel;
    const uint32_t bBaseL = bBaseH + TILE_B;

#pragma unroll
    for (int s = 0; s < 4; ++s) {
      const uint32_t ko = s * 32;
      uint32_t ah[4][4], al[4][4], bh[2][4], bl[2][4];
#pragma unroll
      for (int f = 0; f < 4; ++f) {
        LDSM4(ah[f], aBaseH + f * (16 * 144) + ko);
        LDSM4(al[f], aBaseL + f * (16 * 144) + ko);
      }
#pragma unroll
      for (int g = 0; g < 2; ++g) {
        LDSM4(bh[g], bBaseH + g * (16 * 144) + ko);
        LDSM4(bl[g], bBaseL + g * (16 * 144) + ko);
      }
#pragma unroll
      for (int f = 0; f < 4; ++f) {
#pragma unroll
        for (int j = 0; j < 4; ++j) {
          const int g = j >> 1, hb = j & 1;
          MMA16816(acc[f][j], ah[f], bh[g][hb], bh[g][hb + 2]);
          MMA16816(acc[f][j], ah[f], bl[g][hb], bl[g][hb + 2]);
          MMA16816(acc[f][j], al[f], bh[g][hb], bh[g][hb + 2]);
        }
      }
    }
    __syncthreads();
    if (kt + 2 < nkt) {
      stage_copy(sb, gAh, gAl, gBh, gBl, Kdim, (kt + 2) * 8, tid);
      CP_COMMIT();
    }
  }

  // Epilogue: c0c1 at (row, col..col+1), c2c3 at (row+8, col..col+1)
  const int rbase = bm0 + wm + (lane >> 2);
  const int cbase = bn0 + wn + (lane & 3) * 2;
#pragma unroll
  for (int f = 0; f < 4; ++f) {
#pragma unroll
    for (int j = 0; j < 4; ++j) {
      const int col = cbase + j * 8;
      const float bx = __ldg(&bias[col]);
      const float by = __ldg(&bias[col + 1]);
      const int m0 = rbase + f * 16;
      if (mode == 0) {
        const int which = col >> 10;
        const int h = (col >> 6) & 15;
        const int dh = col & 63;
        float* dst = (which == 0) ? qp : (which == 1) ? kp : vp;
#pragma unroll
        for (int half = 0; half < 2; ++half) {
          const int m = m0 + half * 8;
          const int b = m >> 11, s = m & 2047;
          float2 v2 = make_float2(acc[f][j][half * 2] + bx,
                                  acc[f][j][half * 2 + 1] + by);
          *(float2*)&dst[(size_t)(((b << 4) + h) * 2048 + s) * 64 + dh] = v2;
        }
      } else {
#pragma unroll
        for (int half = 0; half < 2; ++half) {
          const int m = m0 + half * 8;
          float2 v2 = make_float2(acc[f][j][half * 2] + bx,
                                  acc[f][j][half * 2 + 1] + by);
          *(float2*)&outp[(size_t)m * 1024 + col] = v2;
        }
      }
    }
  }
}

// ---------------------------------------------------------------------------
// Fused attention (flash-style), fp32, online softmax. Epilogue writes ctx
// as bf16 hi/lo for the tensor-core out-projection.
// ---------------------------------------------------------------------------
#define SKV 68
#define ATTN_SMEM (4 * 64 * SKV * 4)

__global__ __launch_bounds__(256, 2) void attn_kernel(const int* __restrict__ mask) {
  extern __shared__ float sm[];
  float* Qs = sm;
  float* Ks = sm + 64 * SKV;
  float* Vs = sm + 2 * 64 * SKV;
  float* Ps = sm + 3 * 64 * SKV;

  const int qb = blockIdx.x;
  const int bh = blockIdx.y;
  const int b = bh >> 4;
  const int h = bh & 15;
  const int qm0 = qb * 64;

  const float* Qg = g_q + bh * (S_ * DH_) + qm0 * DH_;
  const float* Kg = g_k + bh * (S_ * DH_);
  const float* Vg = g_v + bh * (S_ * DH_);
  const int* Mg = mask + b * (S_ * S_) + qm0 * S_;

  const int tid = threadIdx.x;
  const int ty = tid >> 4;
  const int tx = tid & 15;
  const int r0 = ty * 4;
  const int cPV = tx * 4;

#pragma unroll
  for (int i = 0; i < 4; ++i) {
    int idx4 = tid + 256 * i;
    int row = idx4 >> 4;
    int col = (idx4 & 15) * 4;
    *(float4*)&Qs[row * SKV + col] = *(const float4*)&Qg[row * 64 + col];
  }

  float O[4][4];
  float mi[4], li[4];
#pragma unroll
  for (int i = 0; i < 4; ++i) {
    mi[i] = -1e30f;
    li[i] = 0.f;
#pragma unroll
    for (int j = 0; j < 4; ++j) O[i][j] = 0.f;
  }

  for (int kn0 = 0; kn0 < S_; kn0 += 64) {
#pragma unroll
    for (int i = 0; i < 4; ++i) {
      int idx4 = tid + 256 * i;
      int row = idx4 >> 4;
      int col = (idx4 & 15) * 4;
      *(float4*)&Ks[row * SKV + col] =
          *(const float4*)&Kg[(kn0 + row) * 64 + col];
      *(float4*)&Vs[row * SKV + col] =
          *(const float4*)&Vg[(kn0 + row) * 64 + col];
    }
    __syncthreads();

    float s[4][4];
#pragma unroll
    for (int i = 0; i < 4; ++i)
#pragma unroll
      for (int j = 0; j < 4; ++j) s[i][j] = 0.f;

#pragma unroll
    for (int k = 0; k < 64; k += 4) {
      float4 qv[4], kv[4];
#pragma unroll
      for (int i = 0; i < 4; ++i)
        qv[i] = *(const float4*)&Qs[(r0 + i) * SKV + k];
#pragma unroll
      for (int j = 0; j < 4; ++j)
        kv[j] = *(const float4*)&Ks[(tx + 16 * j) * SKV + k];
#pragma unroll
      for (int i = 0; i < 4; ++i)
#pragma unroll
        for (int j = 0; j < 4; ++j)
          s[i][j] += qv[i].x * kv[j].x + qv[i].y * kv[j].y +
                     qv[i].z * kv[j].z + qv[i].w * kv[j].w;
    }

#pragma unroll
    for (int i = 0; i < 4; ++i) {
      int row = r0 + i;
      const int* mrow = Mg + row * S_ + kn0;
      float sv[4];
#pragma unroll
      for (int j = 0; j < 4; ++j) {
        int mv = mrow[tx + 16 * j];
        sv[j] = mv ? s[i][j] * 0.125f : -1000.0f;
      }
      float rmax = fmaxf(fmaxf(sv[0], sv[1]), fmaxf(sv[2], sv[3]));
#pragma unroll
      for (int o = 8; o > 0; o >>= 1)
        rmax = fmaxf(rmax, __shfl_xor_sync(0xffffffffu, rmax, o));
      float mnew = fmaxf(mi[i], rmax);
      float corr = __expf(mi[i] - mnew);
      mi[i] = mnew;
      float rsum = 0.f;
#pragma unroll
      for (int j = 0; j < 4; ++j) {
        float p = __expf(sv[j] - mnew);
        rsum += p;
        Ps[row * SKV + tx + 16 * j] = p;
      }
#pragma unroll
      for (int o = 8; o > 0; o >>= 1)
        rsum += __shfl_xor_sync(0xffffffffu, rsum, o);
      li[i] = li[i] * corr + rsum;
      O[i][0] *= corr; O[i][1] *= corr; O[i][2] *= corr; O[i][3] *= corr;
    }
    __syncthreads();

#pragma unroll
    for (int n = 0; n < 64; n += 4) {
      float4 pr[4], vr[4];
#pragma unroll
      for (int i = 0; i < 4; ++i)
        pr[i] = *(const float4*)&Ps[(r0 + i) * SKV + n];
#pragma unroll
      for (int j = 0; j < 4; ++j)
        vr[j] = *(const float4*)&Vs[(n + j) * SKV + cPV];
#pragma unroll
      for (int i = 0; i < 4; ++i) {
        O[i][0] += pr[i].x * vr[0].x + pr[i].y * vr[1].x +
                   pr[i].z * vr[2].x + pr[i].w * vr[3].x;
        O[i][1] += pr[i].x * vr[0].y + pr[i].y * vr[1].y +
                   pr[i].z * vr[2].y + pr[i].w * vr[3].y;
        O[i][2] += pr[i].x * vr[0].z + pr[i].y * vr[1].z +
                   pr[i].z * vr[2].z + pr[i].w * vr[3].z;
        O[i][3] += pr[i].x * vr[0].w + pr[i].y * vr[1].w +
                   pr[i].z * vr[2].w + pr[i].w * vr[3].w;
      }
    }
    __syncthreads();
  }

  // normalize + write ctx (bf16 hi/lo) in [B,S,D] layout
#pragma unroll
  for (int i = 0; i < 4; ++i) {
    float inv = 1.0f / li[i];
    int q = qm0 + r0 + i;
    float vx = O[i][0] * inv, vy = O[i][1] * inv;
    float vz = O[i][2] * inv, vw = O[i][3] * inv;
    size_t base = (size_t)(b * S_ + q) * D_ + h * 64 + cPV;
    __nv_bfloat162 h01, h23, l01, l23;
    h01.x = __float2bfloat16(vx);
    h01.y = __float2bfloat16(vy);
    h23.x = __float2bfloat16(vz);
    h23.y = __float2bfloat16(vw);
    l01.x = __float2bfloat16(vx - __bfloat162float(h01.x));
    l01.y = __float2bfloat16(vy - __bfloat162float(h01.y));
    l23.x = __float2bfloat16(vz - __bfloat162float(h23.x));
    l23.y = __float2bfloat16(vw - __bfloat162float(h23.y));
    *(__nv_bfloat162*)&g_ctxhi[base] = h01;
    *(__nv_bfloat162*)&g_ctxhi[base + 2] = h23;
    *(__nv_bfloat162*)&g_ctxlo[base] = l01;
    *(__nv_bfloat162*)&g_ctxlo[base + 2] = l23;
  }
}

// ---------------------------------------------------------------------------
extern "C" void kernel_launch(void* const* d_in, const int* in_sizes, int n_in,
                              void* d_out, int out_size) {
  const float* x     = (const float*)d_in[0];
  const int*   mask  = (const int*)d_in[1];
  const float* w_qkv = (const float*)d_in[2];
  const float* b_qkv = (const float*)d_in[3];
  const float* w_out = (const float*)d_in[4];
  const float* b_out = (const float*)d_in[5];
  float* out = (float*)d_out;

  void *pxh, *pxl, *pwth, *pwtl, *pwoh, *pwol, *pq, *pk, *pv, *pch, *pcl;
  cudaGetSymbolAddress(&pxh, g_xhi);
  cudaGetSymbolAddress(&pxl, g_xlo);
  cudaGetSymbolAddress(&pwth, g_wthi);
  cudaGetSymbolAddress(&pwtl, g_wtlo);
  cudaGetSymbolAddress(&pwoh, g_wothi);
  cudaGetSymbolAddress(&pwol, g_wotlo);
  cudaGetSymbolAddress(&pq, g_q);
  cudaGetSymbolAddress(&pk, g_k);
  cudaGetSymbolAddress(&pv, g_v);
  cudaGetSymbolAddress(&pch, g_ctxhi);
  cudaGetSymbolAddress(&pcl, g_ctxlo);

  cudaFuncSetAttribute(attn_kernel,
                       cudaFuncAttributeMaxDynamicSharedMemorySize, ATTN_SMEM);
  cudaFuncSetAttribute(mma_gemm,
                       cudaFuncAttributeMaxDynamicSharedMemorySize, GEMM_SMEM);

  // Split/convert inputs
  convert_split<<<(M_ * D_ / 4 + 255) / 256, 256>>>(
      x, M_ * D_ / 4, (__nv_bfloat16*)pxh, (__nv_bfloat16*)pxl);
  transpose_convert<<<dim3(N3D / 32, D_ / 32), dim3(32, 8)>>>(
      w_qkv, D_, N3D, (__nv_bfloat16*)pwth, (__nv_bfloat16*)pwtl);
  transpose_convert<<<dim3(D_ / 32, D_ / 32), dim3(32, 8)>>>(
      w_out, D_, D_, (__nv_bfloat16*)pwoh, (__nv_bfloat16*)pwol);

  // QKV projection (bf16x3 mma.sync), scatter to head-major q/k/v
  mma_gemm<<<dim3(N3D / 128, M_ / 128), 256, GEMM_SMEM>>>(
      (const __nv_bfloat16*)pxh, (const __nv_bfloat16*)pxl,
      (const __nv_bfloat16*)pwth, (const __nv_bfloat16*)pwtl, b_qkv, D_, 0,
      nullptr, (float*)pq, (float*)pk, (float*)pv);

  // Attention (fp32)
  attn_kernel<<<dim3(S_ / 64, B_ * H_), 256, ATTN_SMEM>>>(mask);

  // Output projection (bf16x3 mma.sync)
  mma_gemm<<<dim3(D_ / 128, M_ / 128), 256, GEMM_SMEM>>>(
      (const __nv_bfloat16*)pch, (const __nv_bfloat16*)pcl,
      (const __nv_bfloat16*)pwoh, (const __nv_bfloat16*)pwol, b_out, D_, 1,
      out, nullptr, nullptr, nullptr);
}

// round 9
// speedup vs baseline: 1.2836x; 1.0000x over previous
#include <cuda_runtime.h>
#include <cuda_bf16.h>
#include <cstdint>

// Problem constants
#define B_ 4
#define S_ 2048
#define D_ 1024
#define H_ 16
#define DH_ 64
#define N3D 3072           // 3*D
#define M_ (B_ * S_)       // 8192 rows

// ---------------------------------------------------------------------------
// Device scratch (allocation-free rule)
// ---------------------------------------------------------------------------
__device__ __align__(256) __nv_bfloat16 g_xhi[M_ * D_];
__device__ __align__(256) __nv_bfloat16 g_xlo[M_ * D_];
__device__ __align__(256) __nv_bfloat16 g_wthi[N3D * D_];   // W_qkv^T [n][k]
__device__ __align__(256) __nv_bfloat16 g_wtlo[N3D * D_];
__device__ __align__(256) __nv_bfloat16 g_wothi[D_ * D_];   // W_out^T [n][k]
__device__ __align__(256) __nv_bfloat16 g_wotlo[D_ * D_];
__device__ __align__(256) float g_q[B_ * H_ * S_ * DH_];    // fp32 head-major
__device__ __align__(256) float g_k[B_ * H_ * S_ * DH_];
__device__ __align__(256) float g_v[B_ * H_ * S_ * DH_];
__device__ __align__(256) __nv_bfloat16 g_ctxhi[M_ * D_];   // [b*S+s][d]
__device__ __align__(256) __nv_bfloat16 g_ctxlo[M_ * D_];

// ---------------------------------------------------------------------------
// PTX helpers (sm_80+ standard instructions only — no tcgen05: harness PTX
// target is plain sm_103, 'a'-suffix features are unavailable)
// ---------------------------------------------------------------------------
__device__ __forceinline__ uint32_t smem_to_u32(const void* p) {
  uint32_t a;
  asm("{ .reg .u64 t; cvta.to.shared.u64 t, %1; cvt.u32.u64 %0, t; }"
      : "=r"(a) : "l"(p));
  return a;
}

#define CP_ASYNC16(dst, src)                                              \
  asm volatile("cp.async.cg.shared.global [%0], [%1], 16;" ::"r"(dst),    \
               "l"(src) : "memory")
#define CP_COMMIT() asm volatile("cp.async.commit_group;" ::: "memory")
#define CP_WAIT1() asm volatile("cp.async.wait_group 1;" ::: "memory")
#define CP_WAIT0() asm volatile("cp.async.wait_group 0;" ::: "memory")

#define LDSM4(r, addr)                                                     \
  asm volatile(                                                            \
      "ldmatrix.sync.aligned.m8n8.x4.shared.b16 {%0,%1,%2,%3}, [%4];"      \
      : "=r"((r)[0]), "=r"((r)[1]), "=r"((r)[2]), "=r"((r)[3])             \
      : "r"(addr))

#define MMA16816(c, a, b0, b1)                                              \
  asm volatile(                                                             \
      "mma.sync.aligned.m16n8k16.row.col.f32.bf16.bf16.f32 "                \
      "{%0,%1,%2,%3}, {%4,%5,%6,%7}, {%8,%9}, {%0,%1,%2,%3};"               \
      : "+f"((c)[0]), "+f"((c)[1]), "+f"((c)[2]), "+f"((c)[3])              \
      : "r"((a)[0]), "r"((a)[1]), "r"((a)[2]), "r"((a)[3]), "r"(b0),        \
        "r"(b1))

// ---------------------------------------------------------------------------
// Converter: fp32 -> bf16 hi/lo split (element-wise, vectorized by 4)
// ---------------------------------------------------------------------------
__global__ void convert_split(const float* __restrict__ X, int n4,
                              __nv_bfloat16* __restrict__ hi,
                              __nv_bfloat16* __restrict__ lo) {
  int i = blockIdx.x * blockDim.x + threadIdx.x;
  if (i >= n4) return;
  float4 v = ((const float4*)X)[i];
  __nv_bfloat162 ha, hb, la, lb;
  ha.x = __float2bfloat16(v.x);
  ha.y = __float2bfloat16(v.y);
  hb.x = __float2bfloat16(v.z);
  hb.y = __float2bfloat16(v.w);
  la.x = __float2bfloat16(v.x - __bfloat162float(ha.x));
  la.y = __float2bfloat16(v.y - __bfloat162float(ha.y));
  lb.x = __float2bfloat16(v.z - __bfloat162float(hb.x));
  lb.y = __float2bfloat16(v.w - __bfloat162float(hb.y));
  ((__nv_bfloat162*)hi)[2 * i] = ha;
  ((__nv_bfloat162*)hi)[2 * i + 1] = hb;
  ((__nv_bfloat162*)lo)[2 * i] = la;
  ((__nv_bfloat162*)lo)[2 * i + 1] = lb;
}

// ---------------------------------------------------------------------------
// Converter: transpose W[K][N] -> WT[N][K] with bf16 hi/lo split
// ---------------------------------------------------------------------------
__global__ void transpose_convert(const float* __restrict__ W, int Kd, int Nd,
                                  __nv_bfloat16* __restrict__ WT_hi,
                                  __nv_bfloat16* __restrict__ WT_lo) {
  __shared__ float t[32][33];
  int n0 = blockIdx.x * 32, k0 = blockIdx.y * 32;
  int tx = threadIdx.x;
  for (int r = threadIdx.y; r < 32; r += 8)
    t[r][tx] = W[(size_t)(k0 + r) * Nd + n0 + tx];
  __syncthreads();
  for (int r = threadIdx.y; r < 32; r += 8) {
    float v = t[tx][r];  // = W[k0+tx][n0+r]
    __nv_bfloat16 h = __float2bfloat16(v);
    size_t o = (size_t)(n0 + r) * Kd + k0 + tx;
    WT_hi[o] = h;
    WT_lo[o] = __float2bfloat16(v - __bfloat162float(h));
  }
}

// ---------------------------------------------------------------------------
// bf16x3 GEMM via mma.sync: C[M,N] = A[M,K] @ B^T[N,K] + bias
//   A,B in K-major bf16 hi/lo. 128x128 CTA tile, BK=64, double-buffered
//   cp.async. 8 warps, 64x32 warp tiles, m16n8k16 fragments via ldmatrix.
//   Row pad: 72 bf16 (144 B) -> conflict-free ldmatrix (bank phase 4 per row).
//   mode 0: scatter into head-major g_q/g_k/g_v ; mode 1: row-major out.
// ---------------------------------------------------------------------------
#define TILE_B 18432            // 128 rows * 144 B
#define STAGE_B (4 * TILE_B)    // Ah, Al, Bh, Bl
#define GEMM_SMEM (2 * STAGE_B) // 147456 B

__device__ __forceinline__ void stage_copy(uint32_t sb,
                                           const __nv_bfloat16* gAh,
                                           const __nv_bfloat16* gAl,
                                           const __nv_bfloat16* gBh,
                                           const __nv_bfloat16* gBl,
                                           int Kdim, int kc16, int tid) {
  const __nv_bfloat16* gp[4] = {gAh, gAl, gBh, gBl};
#pragma unroll
  for (int t4 = 0; t4 < 4; ++t4) {
    uint32_t tb = sb + t4 * TILE_B;
    const char* gb = (const char*)gp[t4];
#pragma unroll
    for (int i = 0; i < 4; ++i) {
      int id = tid + 256 * i;          // 1024 chunks: 128 rows x 8 x 16B
      int row = id >> 3, c = id & 7;
      uint32_t dst = tb + row * 144 + c * 16;
      const char* src = gb + ((size_t)row * Kdim + (size_t)(kc16 + c) * 8) * 2;
      CP_ASYNC16(dst, src);
    }
  }
}

__global__ __launch_bounds__(256, 1) void mma_gemm(
    const __nv_bfloat16* __restrict__ Ah, const __nv_bfloat16* __restrict__ Al,
    const __nv_bfloat16* __restrict__ Bh, const __nv_bfloat16* __restrict__ Bl,
    const float* __restrict__ bias, int Kdim, int mode,
    float* __restrict__ outp, float* __restrict__ qp, float* __restrict__ kp,
    float* __restrict__ vp) {
  extern __shared__ __align__(1024) char smem[];
  const uint32_t sm0 = smem_to_u32(smem);
  const int tid = threadIdx.x;
  const int lane = tid & 31;
  const int wid = tid >> 5;
  const int bn0 = blockIdx.x * 128;
  const int bm0 = blockIdx.y * 128;
  const int wm = (wid >> 2) * 64;   // warp m offset in CTA tile
  const int wn = (wid & 3) * 32;    // warp n offset

  const __nv_bfloat16* gAh = Ah + (size_t)bm0 * Kdim;
  const __nv_bfloat16* gAl = Al + (size_t)bm0 * Kdim;
  const __nv_bfloat16* gBh = Bh + (size_t)bn0 * Kdim;
  const __nv_bfloat16* gBl = Bl + (size_t)bn0 * Kdim;

  float acc[4][4][4];
#pragma unroll
  for (int f = 0; f < 4; ++f)
#pragma unroll
    for (int j = 0; j < 4; ++j)
#pragma unroll
      for (int r = 0; r < 4; ++r) acc[f][j][r] = 0.f;

  const int nkt = Kdim >> 6;  // K tiles of 64
  stage_copy(sm0, gAh, gAl, gBh, gBl, Kdim, 0, tid);
  CP_COMMIT();
  stage_copy(sm0 + STAGE_B, gAh, gAl, gBh, gBl, Kdim, 8, tid);
  CP_COMMIT();

  const uint32_t lrow = lane & 15;
  const uint32_t lsel = (lane >> 4) * 16;

  for (int kt = 0; kt < nkt; ++kt) {
    if (kt == nkt - 1) CP_WAIT0(); else CP_WAIT1();
    __syncthreads();
    const uint32_t sb = sm0 + (kt & 1) * STAGE_B;
    const uint32_t aBaseH = sb + (wm + lrow) * 144 + lsel;
    const uint32_t aBaseL = aBaseH + TILE_B;
    const uint32_t bBaseH = sb + 2 * TILE_B + (wn + lrow) * 144 + lsel;
    const uint32_t bBaseL = bBaseH + TILE_B;

#pragma unroll
    for (int s = 0; s < 4; ++s) {
      const uint32_t ko = s * 32;
      uint32_t ah[4][4], al[4][4], bh[2][4], bl[2][4];
#pragma unroll
      for (int f = 0; f < 4; ++f) {
        LDSM4(ah[f], aBaseH + f * (16 * 144) + ko);
        LDSM4(al[f], aBaseL + f * (16 * 144) + ko);
      }
#pragma unroll
      for (int g = 0; g < 2; ++g) {
        LDSM4(bh[g], bBaseH + g * (16 * 144) + ko);
        LDSM4(bl[g], bBaseL + g * (16 * 144) + ko);
      }
#pragma unroll
      for (int f = 0; f < 4; ++f) {
#pragma unroll
        for (int j = 0; j < 4; ++j) {
          const int g = j >> 1, hb = j & 1;
          MMA16816(acc[f][j], ah[f], bh[g][hb], bh[g][hb + 2]);
          MMA16816(acc[f][j], ah[f], bl[g][hb], bl[g][hb + 2]);
          MMA16816(acc[f][j], al[f], bh[g][hb], bh[g][hb + 2]);
        }
      }
    }
    __syncthreads();
    if (kt + 2 < nkt) {
      stage_copy(sb, gAh, gAl, gBh, gBl, Kdim, (kt + 2) * 8, tid);
      CP_COMMIT();
    }
  }

  // Epilogue: c0c1 at (row, col..col+1), c2c3 at (row+8, col..col+1)
  const int rbase = bm0 + wm + (lane >> 2);
  const int cbase = bn0 + wn + (lane & 3) * 2;
#pragma unroll
  for (int f = 0; f < 4; ++f) {
#pragma unroll
    for (int j = 0; j < 4; ++j) {
      const int col = cbase + j * 8;
      const float bx = __ldg(&bias[col]);
      const float by = __ldg(&bias[col + 1]);
      const int m0 = rbase + f * 16;
      if (mode == 0) {
        const int which = col >> 10;
        const int h = (col >> 6) & 15;
        const int dh = col & 63;
        float* dst = (which == 0) ? qp : (which == 1) ? kp : vp;
#pragma unroll
        for (int half = 0; half < 2; ++half) {
          const int m = m0 + half * 8;
          const int b = m >> 11, s = m & 2047;
          float2 v2 = make_float2(acc[f][j][half * 2] + bx,
                                  acc[f][j][half * 2 + 1] + by);
          *(float2*)&dst[(size_t)(((b << 4) + h) * 2048 + s) * 64 + dh] = v2;
        }
      } else {
#pragma unroll
        for (int half = 0; half < 2; ++half) {
          const int m = m0 + half * 8;
          float2 v2 = make_float2(acc[f][j][half * 2] + bx,
                                  acc[f][j][half * 2 + 1] + by);
          *(float2*)&outp[(size_t)m * 1024 + col] = v2;
        }
      }
    }
  }
}

// ---------------------------------------------------------------------------
// Fused attention (flash-style), fp32, online softmax. Epilogue writes ctx
// as bf16 hi/lo for the tensor-core out-projection.
// ---------------------------------------------------------------------------
#define SKV 68
#define ATTN_SMEM (4 * 64 * SKV * 4)

__global__ __launch_bounds__(256, 2) void attn_kernel(const int* __restrict__ mask) {
  extern __shared__ float sm[];
  float* Qs = sm;
  float* Ks = sm + 64 * SKV;
  float* Vs = sm + 2 * 64 * SKV;
  float* Ps = sm + 3 * 64 * SKV;

  const int qb = blockIdx.x;
  const int bh = blockIdx.y;
  const int b = bh >> 4;
  const int h = bh & 15;
  const int qm0 = qb * 64;

  const float* Qg = g_q + bh * (S_ * DH_) + qm0 * DH_;
  const float* Kg = g_k + bh * (S_ * DH_);
  const float* Vg = g_v + bh * (S_ * DH_);
  const int* Mg = mask + b * (S_ * S_) + qm0 * S_;

  const int tid = threadIdx.x;
  const int ty = tid >> 4;
  const int tx = tid & 15;
  const int r0 = ty * 4;
  const int cPV = tx * 4;

#pragma unroll
  for (int i = 0; i < 4; ++i) {
    int idx4 = tid + 256 * i;
    int row = idx4 >> 4;
    int col = (idx4 & 15) * 4;
    *(float4*)&Qs[row * SKV + col] = *(const float4*)&Qg[row * 64 + col];
  }

  float O[4][4];
  float mi[4], li[4];
#pragma unroll
  for (int i = 0; i < 4; ++i) {
    mi[i] = -1e30f;
    li[i] = 0.f;
#pragma unroll
    for (int j = 0; j < 4; ++j) O[i][j] = 0.f;
  }

  for (int kn0 = 0; kn0 < S_; kn0 += 64) {
#pragma unroll
    for (int i = 0; i < 4; ++i) {
      int idx4 = tid + 256 * i;
      int row = idx4 >> 4;
      int col = (idx4 & 15) * 4;
      *(float4*)&Ks[row * SKV + col] =
          *(const float4*)&Kg[(kn0 + row) * 64 + col];
      *(float4*)&Vs[row * SKV + col] =
          *(const float4*)&Vg[(kn0 + row) * 64 + col];
    }
    __syncthreads();

    float s[4][4];
#pragma unroll
    for (int i = 0; i < 4; ++i)
#pragma unroll
      for (int j = 0; j < 4; ++j) s[i][j] = 0.f;

#pragma unroll
    for (int k = 0; k < 64; k += 4) {
      float4 qv[4], kv[4];
#pragma unroll
      for (int i = 0; i < 4; ++i)
        qv[i] = *(const float4*)&Qs[(r0 + i) * SKV + k];
#pragma unroll
      for (int j = 0; j < 4; ++j)
        kv[j] = *(const float4*)&Ks[(tx + 16 * j) * SKV + k];
#pragma unroll
      for (int i = 0; i < 4; ++i)
#pragma unroll
        for (int j = 0; j < 4; ++j)
          s[i][j] += qv[i].x * kv[j].x + qv[i].y * kv[j].y +
                     qv[i].z * kv[j].z + qv[i].w * kv[j].w;
    }

#pragma unroll
    for (int i = 0; i < 4; ++i) {
      int row = r0 + i;
      const int* mrow = Mg + row * S_ + kn0;
      float sv[4];
#pragma unroll
      for (int j = 0; j < 4; ++j) {
        int mv = mrow[tx + 16 * j];
        sv[j] = mv ? s[i][j] * 0.125f : -1000.0f;
      }
      float rmax = fmaxf(fmaxf(sv[0], sv[1]), fmaxf(sv[2], sv[3]));
#pragma unroll
      for (int o = 8; o > 0; o >>= 1)
        rmax = fmaxf(rmax, __shfl_xor_sync(0xffffffffu, rmax, o));
      float mnew = fmaxf(mi[i], rmax);
      float corr = __expf(mi[i] - mnew);
      mi[i] = mnew;
      float rsum = 0.f;
#pragma unroll
      for (int j = 0; j < 4; ++j) {
        float p = __expf(sv[j] - mnew);
        rsum += p;
        Ps[row * SKV + tx + 16 * j] = p;
      }
#pragma unroll
      for (int o = 8; o > 0; o >>= 1)
        rsum += __shfl_xor_sync(0xffffffffu, rsum, o);
      li[i] = li[i] * corr + rsum;
      O[i][0] *= corr; O[i][1] *= corr; O[i][2] *= corr; O[i][3] *= corr;
    }
    __syncthreads();

#pragma unroll
    for (int n = 0; n < 64; n += 4) {
      float4 pr[4], vr[4];
#pragma unroll
      for (int i = 0; i < 4; ++i)
        pr[i] = *(const float4*)&Ps[(r0 + i) * SKV + n];
#pragma unroll
      for (int j = 0; j < 4; ++j)
        vr[j] = *(const float4*)&Vs[(n + j) * SKV + cPV];
#pragma unroll
      for (int i = 0; i < 4; ++i) {
        O[i][0] += pr[i].x * vr[0].x + pr[i].y * vr[1].x +
                   pr[i].z * vr[2].x + pr[i].w * vr[3].x;
        O[i][1] += pr[i].x * vr[0].y + pr[i].y * vr[1].y +
                   pr[i].z * vr[2].y + pr[i].w * vr[3].y;
        O[i][2] += pr[i].x * vr[0].z + pr[i].y * vr[1].z +
                   pr[i].z * vr[2].z + pr[i].w * vr[3].z;
        O[i][3] += pr[i].x * vr[0].w + pr[i].y * vr[1].w +
                   pr[i].z * vr[2].w + pr[i].w * vr[3].w;
      }
    }
    __syncthreads();
  }

  // normalize + write ctx (bf16 hi/lo) in [B,S,D] layout
#pragma unroll
  for (int i = 0; i < 4; ++i) {
    float inv = 1.0f / li[i];
    int q = qm0 + r0 + i;
    float vx = O[i][0] * inv, vy = O[i][1] * inv;
    float vz = O[i][2] * inv, vw = O[i][3] * inv;
    size_t base = (size_t)(b * S_ + q) * D_ + h * 64 + cPV;
    __nv_bfloat162 h01, h23, l01, l23;
    h01.x = __float2bfloat16(vx);
    h01.y = __float2bfloat16(vy);
    h23.x = __float2bfloat16(vz);
    h23.y = __float2bfloat16(vw);
    l01.x = __float2bfloat16(vx - __bfloat162float(h01.x));
    l01.y = __float2bfloat16(vy - __bfloat162float(h01.y));
    l23.x = __float2bfloat16(vz - __bfloat162float(h23.x));
    l23.y = __float2bfloat16(vw - __bfloat162float(h23.y));
    *(__nv_bfloat162*)&g_ctxhi[base] = h01;
    *(__nv_bfloat162*)&g_ctxhi[base + 2] = h23;
    *(__nv_bfloat162*)&g_ctxlo[base] = l01;
    *(__nv_bfloat162*)&g_ctxlo[base + 2] = l23;
  }
}

// ---------------------------------------------------------------------------
extern "C" void kernel_launch(void* const* d_in, const int* in_sizes, int n_in,
                              void* d_out, int out_size) {
  const float* x     = (const float*)d_in[0];
  const int*   mask  = (const int*)d_in[1];
  const float* w_qkv = (const float*)d_in[2];
  const float* b_qkv = (const float*)d_in[3];
  const float* w_out = (const float*)d_in[4];
  const float* b_out = (const float*)d_in[5];
  float* out = (float*)d_out;

  void *pxh, *pxl, *pwth, *pwtl, *pwoh, *pwol, *pq, *pk, *pv, *pch, *pcl;
  cudaGetSymbolAddress(&pxh, g_xhi);
  cudaGetSymbolAddress(&pxl, g_xlo);
  cudaGetSymbolAddress(&pwth, g_wthi);
  cudaGetSymbolAddress(&pwtl, g_wtlo);
  cudaGetSymbolAddress(&pwoh, g_wothi);
  cudaGetSymbolAddress(&pwol, g_wotlo);
  cudaGetSymbolAddress(&pq, g_q);
  cudaGetSymbolAddress(&pk, g_k);
  cudaGetSymbolAddress(&pv, g_v);
  cudaGetSymbolAddress(&pch, g_ctxhi);
  cudaGetSymbolAddress(&pcl, g_ctxlo);

  cudaFuncSetAttribute(attn_kernel,
                       cudaFuncAttributeMaxDynamicSharedMemorySize, ATTN_SMEM);
  cudaFuncSetAttribute(mma_gemm,
                       cudaFuncAttributeMaxDynamicSharedMemorySize, GEMM_SMEM);

  // Split/convert inputs
  convert_split<<<(M_ * D_ / 4 + 255) / 256, 256>>>(
      x, M_ * D_ / 4, (__nv_bfloat16*)pxh, (__nv_bfloat16*)pxl);
  transpose_convert<<<dim3(N3D / 32, D_ / 32), dim3(32, 8)>>>(
      w_qkv, D_, N3D, (__nv_bfloat16*)pwth, (__nv_bfloat16*)pwtl);
  transpose_convert<<<dim3(D_ / 32, D_ / 32), dim3(32, 8)>>>(
      w_out, D_, D_, (__nv_bfloat16*)pwoh, (__nv_bfloat16*)pwol);

  // QKV projection (bf16x3 mma.sync), scatter to head-major q/k/v
  mma_gemm<<<dim3(N3D / 128, M_ / 128), 256, GEMM_SMEM>>>(
      (const __nv_bfloat16*)pxh, (const __nv_bfloat16*)pxl,
      (const __nv_bfloat16*)pwth, (const __nv_bfloat16*)pwtl, b_qkv, D_, 0,
      nullptr, (float*)pq, (float*)pk, (float*)pv);

  // Attention (fp32)
  attn_kernel<<<dim3(S_ / 64, B_ * H_), 256, ATTN_SMEM>>>(mask);

  // Output projection (bf16x3 mma.sync)
  mma_gemm<<<dim3(D_ / 128, M_ / 128), 256, GEMM_SMEM>>>(
      (const __nv_bfloat16*)pch, (const __nv_bfloat16*)pcl,
      (const __nv_bfloat16*)pwoh, (const __nv_bfloat16*)pwol, b_out, D_, 1,
      out, nullptr, nullptr, nullptr);
}

// round 10
// speedup vs baseline: 1.2836x; 1.0000x over previous
#include <cuda_runtime.h>
#include <cuda_bf16.h>
#include <cstdint>

// Problem constants
#define B_ 4
#define S_ 2048
#define D_ 1024
#define H_ 16
#define DH_ 64
#define N3D 3072           // 3*D
#define M_ (B_ * S_)       // 8192 rows

// ---------------------------------------------------------------------------
// Device scratch (allocation-free rule)
// ---------------------------------------------------------------------------
__device__ __align__(256) __nv_bfloat16 g_xhi[M_ * D_];
__device__ __align__(256) __nv_bfloat16 g_xlo[M_ * D_];
__device__ __align__(256) __nv_bfloat16 g_wthi[N3D * D_];   // W_qkv^T [n][k]
__device__ __align__(256) __nv_bfloat16 g_wtlo[N3D * D_];
__device__ __align__(256) __nv_bfloat16 g_wothi[D_ * D_];   // W_out^T [n][k]
__device__ __align__(256) __nv_bfloat16 g_wotlo[D_ * D_];
__device__ __align__(256) float g_q[B_ * H_ * S_ * DH_];    // fp32 head-major
__device__ __align__(256) float g_k[B_ * H_ * S_ * DH_];
__device__ __align__(256) float g_v[B_ * H_ * S_ * DH_];
__device__ __align__(256) __nv_bfloat16 g_ctxhi[M_ * D_];   // [b*S+s][d]
__device__ __align__(256) __nv_bfloat16 g_ctxlo[M_ * D_];

// ---------------------------------------------------------------------------
// PTX helpers (sm_80+ standard instructions only — no tcgen05: harness PTX
// target is plain sm_103, 'a'-suffix features are unavailable)
// ---------------------------------------------------------------------------
__device__ __forceinline__ uint32_t smem_to_u32(const void* p) {
  uint32_t a;
  asm("{ .reg .u64 t; cvta.to.shared.u64 t, %1; cvt.u32.u64 %0, t; }"
      : "=r"(a) : "l"(p));
  return a;
}

#define CP_ASYNC16(dst, src)                                              \
  asm volatile("cp.async.cg.shared.global [%0], [%1], 16;" ::"r"(dst),    \
               "l"(src) : "memory")
#define CP_COMMIT() asm volatile("cp.async.commit_group;" ::: "memory")
#define CP_WAIT1() asm volatile("cp.async.wait_group 1;" ::: "memory")
#define CP_WAIT0() asm volatile("cp.async.wait_group 0;" ::: "memory")

#define LDSM4(r, addr)                                                     \
  asm volatile(                                                            \
      "ldmatrix.sync.aligned.m8n8.x4.shared.b16 {%0,%1,%2,%3}, [%4];"      \
      : "=r"((r)[0]), "=r"((r)[1]), "=r"((r)[2]), "=r"((r)[3])             \
      : "r"(addr))

#define MMA16816(c, a, b0, b1)                                              \
  asm volatile(                                                             \
      "mma.sync.aligned.m16n8k16.row.col.f32.bf16.bf16.f32 "                \
      "{%0,%1,%2,%3}, {%4,%5,%6,%7}, {%8,%9}, {%0,%1,%2,%3};"               \
      : "+f"((c)[0]), "+f"((c)[1]), "+f"((c)[2]), "+f"((c)[3])              \
      : "r"((a)[0]), "r"((a)[1]), "r"((a)[2]), "r"((a)[3]), "r"(b0),        \
        "r"(b1))

// ---------------------------------------------------------------------------
// Converter: fp32 -> bf16 hi/lo split (element-wise, vectorized by 4)
// ---------------------------------------------------------------------------
__global__ void convert_split(const float* __restrict__ X, int n4,
                              __nv_bfloat16* __restrict__ hi,
                              __nv_bfloat16* __restrict__ lo) {
  int i = blockIdx.x * blockDim.x + threadIdx.x;
  if (i >= n4) return;
  float4 v = ((const float4*)X)[i];
  __nv_bfloat162 ha, hb, la, lb;
  ha.x = __float2bfloat16(v.x);
  ha.y = __float2bfloat16(v.y);
  hb.x = __float2bfloat16(v.z);
  hb.y = __float2bfloat16(v.w);
  la.x = __float2bfloat16(v.x - __bfloat162float(ha.x));
  la.y = __float2bfloat16(v.y - __bfloat162float(ha.y));
  lb.x = __float2bfloat16(v.z - __bfloat162float(hb.x));
  lb.y = __float2bfloat16(v.w - __bfloat162float(hb.y));
  ((__nv_bfloat162*)hi)[2 * i] = ha;
  ((__nv_bfloat162*)hi)[2 * i + 1] = hb;
  ((__nv_bfloat162*)lo)[2 * i] = la;
  ((__nv_bfloat162*)lo)[2 * i + 1] = lb;
}

// ---------------------------------------------------------------------------
// Converter: transpose W[K][N] -> WT[N][K] with bf16 hi/lo split
// ---------------------------------------------------------------------------
__global__ void transpose_convert(const float* __restrict__ W, int Kd, int Nd,
                                  __nv_bfloat16* __restrict__ WT_hi,
                                  __nv_bfloat16* __restrict__ WT_lo) {
  __shared__ float t[32][33];
  int n0 = blockIdx.x * 32, k0 = blockIdx.y * 32;
  int tx = threadIdx.x;
  for (int r = threadIdx.y; r < 32; r += 8)
    t[r][tx] = W[(size_t)(k0 + r) * Nd + n0 + tx];
  __syncthreads();
  for (int r = threadIdx.y; r < 32; r += 8) {
    float v = t[tx][r];  // = W[k0+tx][n0+r]
    __nv_bfloat16 h = __float2bfloat16(v);
    size_t o = (size_t)(n0 + r) * Kd + k0 + tx;
    WT_hi[o] = h;
    WT_lo[o] = __float2bfloat16(v - __bfloat162float(h));
  }
}

// ---------------------------------------------------------------------------
// bf16x3 GEMM via mma.sync: C[M,N] = A[M,K] @ B^T[N,K] + bias
//   A,B in K-major bf16 hi/lo. 128x128 CTA tile, BK=64, double-buffered
//   cp.async. 8 warps, 64x32 warp tiles, m16n8k16 fragments via ldmatrix.
//   Row pad: 72 bf16 (144 B) -> conflict-free ldmatrix (bank phase 4 per row).
//   mode 0: scatter into head-major g_q/g_k/g_v ; mode 1: row-major out.
// ---------------------------------------------------------------------------
#define TILE_B 18432            // 128 rows * 144 B
#define STAGE_B (4 * TILE_B)    // Ah, Al, Bh, Bl
#define GEMM_SMEM (2 * STAGE_B) // 147456 B

__device__ __forceinline__ void stage_copy(uint32_t sb,
                                           const __nv_bfloat16* gAh,
                                           const __nv_bfloat16* gAl,
                                           const __nv_bfloat16* gBh,
                                           const __nv_bfloat16* gBl,
                                           int Kdim, int kc16, int tid) {
  const __nv_bfloat16* gp[4] = {gAh, gAl, gBh, gBl};
#pragma unroll
  for (int t4 = 0; t4 < 4; ++t4) {
    uint32_t tb = sb + t4 * TILE_B;
    const char* gb = (const char*)gp[t4];
#pragma unroll
    for (int i = 0; i < 4; ++i) {
      int id = tid + 256 * i;          // 1024 chunks: 128 rows x 8 x 16B
      int row = id >> 3, c = id & 7;
      uint32_t dst = tb + row * 144 + c * 16;
      const char* src = gb + ((size_t)row * Kdim + (size_t)(kc16 + c) * 8) * 2;
      CP_ASYNC16(dst, src);
    }
  }
}

__global__ __launch_bounds__(256, 1) void mma_gemm(
    const __nv_bfloat16* __restrict__ Ah, const __nv_bfloat16* __restrict__ Al,
    const __nv_bfloat16* __restrict__ Bh, const __nv_bfloat16* __restrict__ Bl,
    const float* __restrict__ bias, int Kdim, int mode,
    float* __restrict__ outp, float* __restrict__ qp, float* __restrict__ kp,
    float* __restrict__ vp) {
  extern __shared__ __align__(1024) char smem[];
  const uint32_t sm0 = smem_to_u32(smem);
  const int tid = threadIdx.x;
  const int lane = tid & 31;
  const int wid = tid >> 5;
  const int bn0 = blockIdx.x * 128;
  const int bm0 = blockIdx.y * 128;
  const int wm = (wid >> 2) * 64;   // warp m offset in CTA tile
  const int wn = (wid & 3) * 32;    // warp n offset

  const __nv_bfloat16* gAh = Ah + (size_t)bm0 * Kdim;
  const __nv_bfloat16* gAl = Al + (size_t)bm0 * Kdim;
  const __nv_bfloat16* gBh = Bh + (size_t)bn0 * Kdim;
  const __nv_bfloat16* gBl = Bl + (size_t)bn0 * Kdim;

  float acc[4][4][4];
#pragma unroll
  for (int f = 0; f < 4; ++f)
#pragma unroll
    for (int j = 0; j < 4; ++j)
#pragma unroll
      for (int r = 0; r < 4; ++r) acc[f][j][r] = 0.f;

  const int nkt = Kdim >> 6;  // K tiles of 64
  stage_copy(sm0, gAh, gAl, gBh, gBl, Kdim, 0, tid);
  CP_COMMIT();
  stage_copy(sm0 + STAGE_B, gAh, gAl, gBh, gBl, Kdim, 8, tid);
  CP_COMMIT();

  const uint32_t lrow = lane & 15;
  const uint32_t lsel = (lane >> 4) * 16;

  for (int kt = 0; kt < nkt; ++kt) {
    if (kt == nkt - 1) CP_WAIT0(); else CP_WAIT1();
    __syncthreads();
    const uint32_t sb = sm0 + (kt & 1) * STAGE_B;
    const uint32_t aBaseH = sb + (wm + lrow) * 144 + lsel;
    const uint32_t aBaseL = aBaseH + TILE_B;
    const uint32_t bBaseH = sb + 2 * TILE_B + (wn + lrow) * 144 + lsel;
    const uint32_t bBaseL = bBaseH + TILE_B;

#pragma unroll
    for (int s = 0; s < 4; ++s) {
      const uint32_t ko = s * 32;
      uint32_t ah[4][4], al[4][4], bh[2][4], bl[2][4];
#pragma unroll
      for (int f = 0; f < 4; ++f) {
        LDSM4(ah[f], aBaseH + f * (16 * 144) + ko);
        LDSM4(al[f], aBaseL + f * (16 * 144) + ko);
      }
#pragma unroll
      for (int g = 0; g < 2; ++g) {
        LDSM4(bh[g], bBaseH + g * (16 * 144) + ko);
        LDSM4(bl[g], bBaseL + g * (16 * 144) + ko);
      }
#pragma unroll
      for (int f = 0; f < 4; ++f) {
#pragma unroll
        for (int j = 0; j < 4; ++j) {
          const int g = j >> 1, hb = j & 1;
          MMA16816(acc[f][j], ah[f], bh[g][hb], bh[g][hb + 2]);
          MMA16816(acc[f][j], ah[f], bl[g][hb], bl[g][hb + 2]);
          MMA16816(acc[f][j], al[f], bh[g][hb], bh[g][hb + 2]);
        }
      }
    }
    __syncthreads();
    if (kt + 2 < nkt) {
      stage_copy(sb, gAh, gAl, gBh, gBl, Kdim, (kt + 2) * 8, tid);
      CP_COMMIT();
    }
  }

  // Epilogue: c0c1 at (row, col..col+1), c2c3 at (row+8, col..col+1)
  const int rbase = bm0 + wm + (lane >> 2);
  const int cbase = bn0 + wn + (lane & 3) * 2;
#pragma unroll
  for (int f = 0; f < 4; ++f) {
#pragma unroll
    for (int j = 0; j < 4; ++j) {
      const int col = cbase + j * 8;
      const float bx = __ldg(&bias[col]);
      const float by = __ldg(&bias[col + 1]);
      const int m0 = rbase + f * 16;
      if (mode == 0) {
        const int which = col >> 10;
        const int h = (col >> 6) & 15;
        const int dh = col & 63;
        float* dst = (which == 0) ? qp : (which == 1) ? kp : vp;
#pragma unroll
        for (int half = 0; half < 2; ++half) {
          const int m = m0 + half * 8;
          const int b = m >> 11, s = m & 2047;
          float2 v2 = make_float2(acc[f][j][half * 2] + bx,
                                  acc[f][j][half * 2 + 1] + by);
          *(float2*)&dst[(size_t)(((b << 4) + h) * 2048 + s) * 64 + dh] = v2;
        }
      } else {
#pragma unroll
        for (int half = 0; half < 2; ++half) {
          const int m = m0 + half * 8;
          float2 v2 = make_float2(acc[f][j][half * 2] + bx,
                                  acc[f][j][half * 2 + 1] + by);
          *(float2*)&outp[(size_t)m * 1024 + col] = v2;
        }
      }
    }
  }
}

// ---------------------------------------------------------------------------
// Fused attention (flash-style), fp32, online softmax. Epilogue writes ctx
// as bf16 hi/lo for the tensor-core out-projection.
// ---------------------------------------------------------------------------
#define SKV 68
#define ATTN_SMEM (4 * 64 * SKV * 4)

__global__ __launch_bounds__(256, 2) void attn_kernel(const int* __restrict__ mask) {
  extern __shared__ float sm[];
  float* Qs = sm;
  float* Ks = sm + 64 * SKV;
  float* Vs = sm + 2 * 64 * SKV;
  float* Ps = sm + 3 * 64 * SKV;

  const int qb = blockIdx.x;
  const int bh = blockIdx.y;
  const int b = bh >> 4;
  const int h = bh & 15;
  const int qm0 = qb * 64;

  const float* Qg = g_q + bh * (S_ * DH_) + qm0 * DH_;
  const float* Kg = g_k + bh * (S_ * DH_);
  const float* Vg = g_v + bh * (S_ * DH_);
  const int* Mg = mask + b * (S_ * S_) + qm0 * S_;

  const int tid = threadIdx.x;
  const int ty = tid >> 4;
  const int tx = tid & 15;
  const int r0 = ty * 4;
  const int cPV = tx * 4;

#pragma unroll
  for (int i = 0; i < 4; ++i) {
    int idx4 = tid + 256 * i;
    int row = idx4 >> 4;
    int col = (idx4 & 15) * 4;
    *(float4*)&Qs[row * SKV + col] = *(const float4*)&Qg[row * 64 + col];
  }

  float O[4][4];
  float mi[4], li[4];
#pragma unroll
  for (int i = 0; i < 4; ++i) {
    mi[i] = -1e30f;
    li[i] = 0.f;
#pragma unroll
    for (int j = 0; j < 4; ++j) O[i][j] = 0.f;
  }

  for (int kn0 = 0; kn0 < S_; kn0 += 64) {
#pragma unroll
    for (int i = 0; i < 4; ++i) {
      int idx4 = tid + 256 * i;
      int row = idx4 >> 4;
      int col = (idx4 & 15) * 4;
      *(float4*)&Ks[row * SKV + col] =
          *(const float4*)&Kg[(kn0 + row) * 64 + col];
      *(float4*)&Vs[row * SKV + col] =
          *(const float4*)&Vg[(kn0 + row) * 64 + col];
    }
    __syncthreads();

    float s[4][4];
#pragma unroll
    for (int i = 0; i < 4; ++i)
#pragma unroll
      for (int j = 0; j < 4; ++j) s[i][j] = 0.f;

#pragma unroll
    for (int k = 0; k < 64; k += 4) {
      float4 qv[4], kv[4];
#pragma unroll
      for (int i = 0; i < 4; ++i)
        qv[i] = *(const float4*)&Qs[(r0 + i) * SKV + k];
#pragma unroll
      for (int j = 0; j < 4; ++j)
        kv[j] = *(const float4*)&Ks[(tx + 16 * j) * SKV + k];
#pragma unroll
      for (int i = 0; i < 4; ++i)
#pragma unroll
        for (int j = 0; j < 4; ++j)
          s[i][j] += qv[i].x * kv[j].x + qv[i].y * kv[j].y +
                     qv[i].z * kv[j].z + qv[i].w * kv[j].w;
    }

#pragma unroll
    for (int i = 0; i < 4; ++i) {
      int row = r0 + i;
      const int* mrow = Mg + row * S_ + kn0;
      float sv[4];
#pragma unroll
      for (int j = 0; j < 4; ++j) {
        int mv = mrow[tx + 16 * j];
        sv[j] = mv ? s[i][j] * 0.125f : -1000.0f;
      }
      float rmax = fmaxf(fmaxf(sv[0], sv[1]), fmaxf(sv[2], sv[3]));
#pragma unroll
      for (int o = 8; o > 0; o >>= 1)
        rmax = fmaxf(rmax, __shfl_xor_sync(0xffffffffu, rmax, o));
      float mnew = fmaxf(mi[i], rmax);
      float corr = __expf(mi[i] - mnew);
      mi[i] = mnew;
      float rsum = 0.f;
#pragma unroll
      for (int j = 0; j < 4; ++j) {
        float p = __expf(sv[j] - mnew);
        rsum += p;
        Ps[row * SKV + tx + 16 * j] = p;
      }
#pragma unroll
      for (int o = 8; o > 0; o >>= 1)
        rsum += __shfl_xor_sync(0xffffffffu, rsum, o);
      li[i] = li[i] * corr + rsum;
      O[i][0] *= corr; O[i][1] *= corr; O[i][2] *= corr; O[i][3] *= corr;
    }
    __syncthreads();

#pragma unroll
    for (int n = 0; n < 64; n += 4) {
      float4 pr[4], vr[4];
#pragma unroll
      for (int i = 0; i < 4; ++i)
        pr[i] = *(const float4*)&Ps[(r0 + i) * SKV + n];
#pragma unroll
      for (int j = 0; j < 4; ++j)
        vr[j] = *(const float4*)&Vs[(n + j) * SKV + cPV];
#pragma unroll
      for (int i = 0; i < 4; ++i) {
        O[i][0] += pr[i].x * vr[0].x + pr[i].y * vr[1].x +
                   pr[i].z * vr[2].x + pr[i].w * vr[3].x;
        O[i][1] += pr[i].x * vr[0].y + pr[i].y * vr[1].y +
                   pr[i].z * vr[2].y + pr[i].w * vr[3].y;
        O[i][2] += pr[i].x * vr[0].z + pr[i].y * vr[1].z +
                   pr[i].z * vr[2].z + pr[i].w * vr[3].z;
        O[i][3] += pr[i].x * vr[0].w + pr[i].y * vr[1].w +
                   pr[i].z * vr[2].w + pr[i].w * vr[3].w;
      }
    }
    __syncthreads();
  }

  // normalize + write ctx (bf16 hi/lo) in [B,S,D] layout
#pragma unroll
  for (int i = 0; i < 4; ++i) {
    float inv = 1.0f / li[i];
    int q = qm0 + r0 + i;
    float vx = O[i][0] * inv, vy = O[i][1] * inv;
    float vz = O[i][2] * inv, vw = O[i][3] * inv;
    size_t base = (size_t)(b * S_ + q) * D_ + h * 64 + cPV;
    __nv_bfloat162 h01, h23, l01, l23;
    h01.x = __float2bfloat16(vx);
    h01.y = __float2bfloat16(vy);
    h23.x = __float2bfloat16(vz);
    h23.y = __float2bfloat16(vw);
    l01.x = __float2bfloat16(vx - __bfloat162float(h01.x));
    l01.y = __float2bfloat16(vy - __bfloat162float(h01.y));
    l23.x = __float2bfloat16(vz - __bfloat162float(h23.x));
    l23.y = __float2bfloat16(vw - __bfloat162float(h23.y));
    *(__nv_bfloat162*)&g_ctxhi[base] = h01;
    *(__nv_bfloat162*)&g_ctxhi[base + 2] = h23;
    *(__nv_bfloat162*)&g_ctxlo[base] = l01;
    *(__nv_bfloat162*)&g_ctxlo[base + 2] = l23;
  }
}

// ---------------------------------------------------------------------------
extern "C" void kernel_launch(void* const* d_in, const int* in_sizes, int n_in,
                              void* d_out, int out_size) {
  const float* x     = (const float*)d_in[0];
  const int*   mask  = (const int*)d_in[1];
  const float* w_qkv = (const float*)d_in[2];
  const float* b_qkv = (const float*)d_in[3];
  const float* w_out = (const float*)d_in[4];
  const float* b_out = (const float*)d_in[5];
  float* out = (float*)d_out;

  void *pxh, *pxl, *pwth, *pwtl, *pwoh, *pwol, *pq, *pk, *pv, *pch, *pcl;
  cudaGetSymbolAddress(&pxh, g_xhi);
  cudaGetSymbolAddress(&pxl, g_xlo);
  cudaGetSymbolAddress(&pwth, g_wthi);
  cudaGetSymbolAddress(&pwtl, g_wtlo);
  cudaGetSymbolAddress(&pwoh, g_wothi);
  cudaGetSymbolAddress(&pwol, g_wotlo);
  cudaGetSymbolAddress(&pq, g_q);
  cudaGetSymbolAddress(&pk, g_k);
  cudaGetSymbolAddress(&pv, g_v);
  cudaGetSymbolAddress(&pch, g_ctxhi);
  cudaGetSymbolAddress(&pcl, g_ctxlo);

  cudaFuncSetAttribute(attn_kernel,
                       cudaFuncAttributeMaxDynamicSharedMemorySize, ATTN_SMEM);
  cudaFuncSetAttribute(mma_gemm,
                       cudaFuncAttributeMaxDynamicSharedMemorySize, GEMM_SMEM);

  // Split/convert inputs
  convert_split<<<(M_ * D_ / 4 + 255) / 256, 256>>>(
      x, M_ * D_ / 4, (__nv_bfloat16*)pxh, (__nv_bfloat16*)pxl);
  transpose_convert<<<dim3(N3D / 32, D_ / 32), dim3(32, 8)>>>(
      w_qkv, D_, N3D, (__nv_bfloat16*)pwth, (__nv_bfloat16*)pwtl);
  transpose_convert<<<dim3(D_ / 32, D_ / 32), dim3(32, 8)>>>(
      w_out, D_, D_, (__nv_bfloat16*)pwoh, (__nv_bfloat16*)pwol);

  // QKV projection (bf16x3 mma.sync), scatter to head-major q/k/v
  mma_gemm<<<dim3(N3D / 128, M_ / 128), 256, GEMM_SMEM>>>(
      (const __nv_bfloat16*)pxh, (const __nv_bfloat16*)pxl,
      (const __nv_bfloat16*)pwth, (const __nv_bfloat16*)pwtl, b_qkv, D_, 0,
      nullptr, (float*)pq, (float*)pk, (float*)pv);

  // Attention (fp32)
  attn_kernel<<<dim3(S_ / 64, B_ * H_), 256, ATTN_SMEM>>>(mask);

  // Output projection (bf16x3 mma.sync)
  mma_gemm<<<dim3(D_ / 128, M_ / 128), 256, GEMM_SMEM>>>(
      (const __nv_bfloat16*)pch, (const __nv_bfloat16*)pcl,
      (const __nv_bfloat16*)pwoh, (const __nv_bfloat16*)pwol, b_out, D_, 1,
      out, nullptr, nullptr, nullptr);
}